// round 1
// baseline (speedup 1.0000x reference)
#include <cuda_runtime.h>
#include <cuda_bf16.h>

// Problem constants
#define BB 4
#define HH 64
#define WW 64
#define CC_ 256
#define FF 256
#define HWSZ 4096          // H*W
#define NPIX 16384         // B*H*W
#define KK9 9

// Scratch (allocation-free: __device__ globals)
__device__ float  g_wT[KK9 * CC_ * FF];    // [kk][c][f], 2.36 MB
__device__ int4   g_midx[KK9 * NPIX];      // corner element offsets (pre-multiplied by C, incl. batch)
__device__ float4 g_mw[KK9 * NPIX];        // bilinear*mask*valid weights

// ---------------------------------------------------------------------------
// Kernel 1: transpose filt [F,C,9] -> wT [9][C][F]
// ---------------------------------------------------------------------------
__global__ void transpose_filt_kernel(const float* __restrict__ filt) {
    int i = blockIdx.x * 256 + threadIdx.x;      // over 9*256*256 = 589824
    int f  = i & 255;
    int c  = (i >> 8) & 255;
    int kk = i >> 16;
    g_wT[i] = filt[(f * 256 + c) * 9 + kk];
}

// ---------------------------------------------------------------------------
// Kernel 2: offset conv (3x3, C->27, SAME) + sampling metadata
// Block: 256 threads = 8 warps; warp handles 2 pixels, lanes = 32 channels.
// Weights staged in smem in chunks of 32 channels, pitch 29 (conflict-free).
// ---------------------------------------------------------------------------
__global__ __launch_bounds__(256) void offset_meta_kernel(
    const float* __restrict__ x, const float* __restrict__ w_off,
    const float* __restrict__ b_off) {
    __shared__ float ws[9 * 32 * 29];        // [tap][cl][o] pitch 29
    __shared__ float wi_s[8][2][27];

    const int tid  = threadIdx.x;
    const int warp = tid >> 5;
    const int lane = tid & 31;
    const int p0   = blockIdx.x * 16 + warp * 2;   // first of 2 pixels

    int b_[2], yy_[2], xx_[2];
#pragma unroll
    for (int q = 0; q < 2; ++q) {
        int gp = p0 + q;
        b_[q]  = gp >> 12;
        int r  = gp & 4095;
        yy_[q] = r >> 6;
        xx_[q] = r & 63;
    }

    float acc0[27], acc1[27];
#pragma unroll
    for (int o = 0; o < 27; ++o) { acc0[o] = 0.f; acc1[o] = 0.f; }

    for (int cc = 0; cc < 8; ++cc) {
        __syncthreads();
        // load weight chunk: w_off[(tap*256 + cc*32 + cl)*27 + o]
        for (int i = tid; i < 9 * 32 * 27; i += 256) {
            int tap = i / 864;
            int r   = i - tap * 864;
            int cl  = r / 27;
            int o   = r - cl * 27;
            ws[(tap * 32 + cl) * 29 + o] = w_off[(tap * 256 + cc * 32 + cl) * 27 + o];
        }
        __syncthreads();

        const int c = cc * 32 + lane;
#pragma unroll
        for (int tap = 0; tap < 9; ++tap) {
            const int ki = tap / 3, kj = tap % 3;
            float xv0, xv1;
            {
                int yy = yy_[0] - 1 + ki, xc = xx_[0] - 1 + kj;
                xv0 = ((unsigned)yy < 64u && (unsigned)xc < 64u)
                          ? __ldg(x + (((b_[0] << 12) + (yy << 6) + xc) << 8) + c) : 0.f;
            }
            {
                int yy = yy_[1] - 1 + ki, xc = xx_[1] - 1 + kj;
                xv1 = ((unsigned)yy < 64u && (unsigned)xc < 64u)
                          ? __ldg(x + (((b_[1] << 12) + (yy << 6) + xc) << 8) + c) : 0.f;
            }
            const float* wrow = &ws[(tap * 32 + lane) * 29];
#pragma unroll
            for (int o = 0; o < 27; ++o) {
                float wv = wrow[o];
                acc0[o] += wv * xv0;
                acc1[o] += wv * xv1;
            }
        }
    }

    // warp reduce over channel lanes
#pragma unroll
    for (int o = 0; o < 27; ++o) {
        float s0 = acc0[o], s1 = acc1[o];
#pragma unroll
        for (int sft = 16; sft; sft >>= 1) {
            s0 += __shfl_xor_sync(0xffffffffu, s0, sft);
            s1 += __shfl_xor_sync(0xffffffffu, s1, sft);
        }
        if (lane == 0) { wi_s[warp][0][o] = s0; wi_s[warp][1][o] = s1; }
    }
    __syncwarp();

    // lanes 0..8 -> taps of pixel 0; lanes 16..24 -> taps of pixel 1
    int q = -1, kk = 0;
    if (lane < 9)                     { q = 0; kk = lane; }
    else if (lane >= 16 && lane < 25) { q = 1; kk = lane - 16; }

    if (q >= 0) {
        float o1v = wi_s[warp][q][kk]      + __ldg(b_off + kk);
        float o2v = wi_s[warp][q][9 + kk]  + __ldg(b_off + 9 + kk);
        float mlg = wi_s[warp][q][18 + kk] + __ldg(b_off + 18 + kk);
        float mv  = 1.f / (1.f + __expf(-mlg));

        float pyv = o1v + (float)(yy_[q] - 1 + kk / 3);
        float pxv = o2v + (float)(xx_[q] - 1 + kk % 3);
        float yf = floorf(pyv), xf = floorf(pxv);
        float dy = pyv - yf, dx = pxv - xf;
        int iy = (int)yf, ix = (int)xf;

        int base = b_[q] << 12;
        int yc0 = min(max(iy, 0), 63),     yc1 = min(max(iy + 1, 0), 63);
        int xc0 = min(max(ix, 0), 63),     xc1 = min(max(ix + 1, 0), 63);
        float vy0 = ((unsigned)iy       < 64u) ? 1.f : 0.f;
        float vy1 = ((unsigned)(iy + 1) < 64u) ? 1.f : 0.f;
        float vx0 = ((unsigned)ix       < 64u) ? 1.f : 0.f;
        float vx1 = ((unsigned)(ix + 1) < 64u) ? 1.f : 0.f;

        int4 mi = make_int4(((base + (yc0 << 6) + xc0) << 8),
                            ((base + (yc0 << 6) + xc1) << 8),
                            ((base + (yc1 << 6) + xc0) << 8),
                            ((base + (yc1 << 6) + xc1) << 8));
        float4 mw = make_float4((1.f - dy) * (1.f - dx) * mv * vy0 * vx0,
                                (1.f - dy) * dx         * mv * vy0 * vx1,
                                dy         * (1.f - dx) * mv * vy1 * vx0,
                                dy         * dx         * mv * vy1 * vx1);
        int gp = p0 + q;
        g_midx[kk * NPIX + gp] = mi;
        g_mw[kk * NPIX + gp]   = mw;
    }
}

// ---------------------------------------------------------------------------
// Kernel 3: fused implicit-im2col GEMM.
// Tile: 64 pixels x 128 filters, K loop = 9 taps x 8 chunks of 32 channels.
// 256 threads; each computes 4p x 8f. Gather mapping: thread = (pixel, c-quad)
// so warp-LDG.128 touches ~8 lines (coalesced along channels).
// ---------------------------------------------------------------------------
__global__ __launch_bounds__(256) void dcn_gemm_kernel(
    const float* __restrict__ x, float* __restrict__ out) {
    __shared__ float  bs[32 * 128];
    __shared__ float  as[32 * 64];
    __shared__ int4   mi_s[64];
    __shared__ float4 mw_s[64];

    const int tid = threadIdx.x;
    const int p0 = blockIdx.x * 64;
    const int f0 = blockIdx.y * 128;
    const int fi = (tid & 15) * 8;
    const int pi = (tid >> 4) * 4;
    const int gpix = tid >> 2;   // 0..63 pixel-local for gather
    const int cq   = tid & 3;    // channel quad

    float acc[4][8];
#pragma unroll
    for (int a = 0; a < 4; ++a)
#pragma unroll
        for (int b2 = 0; b2 < 8; ++b2) acc[a][b2] = 0.f;

    for (int kk = 0; kk < 9; ++kk) {
        __syncthreads();
        if (tid < 64) {
            mi_s[tid] = g_midx[kk * NPIX + p0 + tid];
            mw_s[tid] = g_mw[kk * NPIX + p0 + tid];
        }
        __syncthreads();
        const int4   mi  = mi_s[gpix];
        const float4 mwv = mw_s[gpix];

        for (int cc = 0; cc < 8; ++cc) {
            // --- gather A fragment into registers ---
            float4 va[2];
#pragma unroll
            for (int j = 0; j < 2; ++j) {
                int c = cc * 32 + cq * 4 + j * 16;
                float4 v00 = __ldg((const float4*)(x + mi.x + c));
                float4 v01 = __ldg((const float4*)(x + mi.y + c));
                float4 v10 = __ldg((const float4*)(x + mi.z + c));
                float4 v11 = __ldg((const float4*)(x + mi.w + c));
                va[j].x = v00.x * mwv.x + v01.x * mwv.y + v10.x * mwv.z + v11.x * mwv.w;
                va[j].y = v00.y * mwv.x + v01.y * mwv.y + v10.y * mwv.z + v11.y * mwv.w;
                va[j].z = v00.z * mwv.x + v01.z * mwv.y + v10.z * mwv.z + v11.z * mwv.w;
                va[j].w = v00.w * mwv.x + v01.w * mwv.y + v10.w * mwv.z + v11.w * mwv.w;
            }
            // --- load B tile (32 x 128) into registers ---
            float4 vb[4];
            const float* bbase = g_wT + (kk * 256 + cc * 32) * 256 + f0;
#pragma unroll
            for (int i2 = 0; i2 < 4; ++i2) {
                int qq   = tid + i2 * 256;   // 0..1023 float4 index in tile
                int row  = qq >> 5;
                int col4 = qq & 31;
                vb[i2] = __ldg((const float4*)(bbase + row * 256) + col4);
            }
            __syncthreads();
#pragma unroll
            for (int i2 = 0; i2 < 4; ++i2) ((float4*)bs)[tid + i2 * 256] = vb[i2];
#pragma unroll
            for (int j = 0; j < 2; ++j) {
                int cl = cq * 4 + j * 16;
                as[(cl + 0) * 64 + gpix] = va[j].x;
                as[(cl + 1) * 64 + gpix] = va[j].y;
                as[(cl + 2) * 64 + gpix] = va[j].z;
                as[(cl + 3) * 64 + gpix] = va[j].w;
            }
            __syncthreads();
            // --- FMA ---
#pragma unroll
            for (int k = 0; k < 32; ++k) {
                float bfr[8], afr[4];
                *(float4*)&bfr[0] = *(const float4*)&bs[k * 128 + fi];
                *(float4*)&bfr[4] = *(const float4*)&bs[k * 128 + fi + 4];
                *(float4*)&afr[0] = *(const float4*)&as[k * 64 + pi];
#pragma unroll
                for (int a = 0; a < 4; ++a)
#pragma unroll
                    for (int b2 = 0; b2 < 8; ++b2)
                        acc[a][b2] += afr[a] * bfr[b2];
            }
        }
    }

    // epilogue: out[b,y,x,f] = out[gp*256 + f]
#pragma unroll
    for (int a = 0; a < 4; ++a) {
        float* op = out + (p0 + pi + a) * 256 + f0 + fi;
        *(float4*)op       = make_float4(acc[a][0], acc[a][1], acc[a][2], acc[a][3]);
        *(float4*)(op + 4) = make_float4(acc[a][4], acc[a][5], acc[a][6], acc[a][7]);
    }
}

// ---------------------------------------------------------------------------
extern "C" void kernel_launch(void* const* d_in, const int* in_sizes, int n_in,
                              void* d_out, int out_size) {
    const float* x     = (const float*)d_in[0];   // [4,64,64,256]
    const float* w_off = (const float*)d_in[1];   // [3,3,256,27]
    const float* b_off = (const float*)d_in[2];   // [27]
    const float* filt  = (const float*)d_in[3];   // [256,256,3,3]
    float* out = (float*)d_out;                   // [4,64,64,256]

    transpose_filt_kernel<<<2304, 256>>>(filt);
    offset_meta_kernel<<<1024, 256>>>(x, w_off, b_off);
    dcn_gemm_kernel<<<dim3(256, 2), 256>>>(x, out);
}

// round 3
// speedup vs baseline: 1.8410x; 1.8410x over previous
#include <cuda_runtime.h>
#include <cuda_bf16.h>
#include <cstdint>

// Problem constants
#define NPIX 16384         // B*H*W = 4*64*64
#define KK9 9

// Scratch (allocation-free: __device__ globals)
__device__ int4   g_midx[KK9 * NPIX];        // corner element offsets (pre-multiplied by C)
__device__ float4 g_mw[KK9 * NPIX];          // bilinear*mask*valid weights
// B operand, split bf16 hi/lo, layout [kk][cc(4)][fb(2)] blocks of [128 f][72 ch] (pad 64->72)
__device__ __nv_bfloat16 g_wbhi[KK9 * 4 * 2 * 128 * 72];
__device__ __nv_bfloat16 g_wblo[KK9 * 4 * 2 * 128 * 72];

__device__ __forceinline__ uint32_t smem_u32(const void* p) {
    uint32_t a;
    asm("{ .reg .u64 t; cvta.to.shared.u64 t, %1; cvt.u32.u64 %0, t; }" : "=r"(a) : "l"(p));
    return a;
}

// ---------------------------------------------------------------------------
// Kernel 1: split filt [F,C,3,3] -> bf16 hi/lo in [blk][f(128)][72] layout
// ---------------------------------------------------------------------------
__global__ void split_filt_kernel(const float* __restrict__ filt) {
    int i = blockIdx.x * 256 + threadIdx.x;    // 9*256*256
    int f  = i & 255;
    int c  = (i >> 8) & 255;
    int kk = i >> 16;
    float w = filt[(f * 256 + c) * 9 + kk];
    __nv_bfloat16 hi = __float2bfloat16(w);
    __nv_bfloat16 lo = __float2bfloat16(w - __bfloat162float(hi));
    int cc = c >> 6, col = c & 63, fb = f >> 7, row = f & 127;
    int blk = (kk * 4 + cc) * 2 + fb;
    int idx = blk * (128 * 72) + row * 72 + col;
    g_wbhi[idx] = hi;
    g_wblo[idx] = lo;
}

// ---------------------------------------------------------------------------
// Kernel 2: offset conv (3x3, C->27, SAME) + sampling metadata (proven R1)
// ---------------------------------------------------------------------------
__global__ __launch_bounds__(256) void offset_meta_kernel(
    const float* __restrict__ x, const float* __restrict__ w_off,
    const float* __restrict__ b_off) {
    __shared__ float ws[9 * 32 * 29];
    __shared__ float wi_s[8][2][27];

    const int tid  = threadIdx.x;
    const int warp = tid >> 5;
    const int lane = tid & 31;
    const int p0   = blockIdx.x * 16 + warp * 2;

    int b_[2], yy_[2], xx_[2];
#pragma unroll
    for (int q = 0; q < 2; ++q) {
        int gp = p0 + q;
        b_[q]  = gp >> 12;
        int r  = gp & 4095;
        yy_[q] = r >> 6;
        xx_[q] = r & 63;
    }

    float acc0[27], acc1[27];
#pragma unroll
    for (int o = 0; o < 27; ++o) { acc0[o] = 0.f; acc1[o] = 0.f; }

    for (int cc = 0; cc < 8; ++cc) {
        __syncthreads();
        for (int i = tid; i < 9 * 32 * 27; i += 256) {
            int tap = i / 864;
            int r   = i - tap * 864;
            int cl  = r / 27;
            int o   = r - cl * 27;
            ws[(tap * 32 + cl) * 29 + o] = w_off[(tap * 256 + cc * 32 + cl) * 27 + o];
        }
        __syncthreads();

        const int c = cc * 32 + lane;
#pragma unroll
        for (int tap = 0; tap < 9; ++tap) {
            const int ki = tap / 3, kj = tap % 3;
            float xv0, xv1;
            {
                int yy = yy_[0] - 1 + ki, xc = xx_[0] - 1 + kj;
                xv0 = ((unsigned)yy < 64u && (unsigned)xc < 64u)
                          ? __ldg(x + (((b_[0] << 12) + (yy << 6) + xc) << 8) + c) : 0.f;
            }
            {
                int yy = yy_[1] - 1 + ki, xc = xx_[1] - 1 + kj;
                xv1 = ((unsigned)yy < 64u && (unsigned)xc < 64u)
                          ? __ldg(x + (((b_[1] << 12) + (yy << 6) + xc) << 8) + c) : 0.f;
            }
            const float* wrow = &ws[(tap * 32 + lane) * 29];
#pragma unroll
            for (int o = 0; o < 27; ++o) {
                float wv = wrow[o];
                acc0[o] += wv * xv0;
                acc1[o] += wv * xv1;
            }
        }
    }

#pragma unroll
    for (int o = 0; o < 27; ++o) {
        float s0 = acc0[o], s1 = acc1[o];
#pragma unroll
        for (int sft = 16; sft; sft >>= 1) {
            s0 += __shfl_xor_sync(0xffffffffu, s0, sft);
            s1 += __shfl_xor_sync(0xffffffffu, s1, sft);
        }
        if (lane == 0) { wi_s[warp][0][o] = s0; wi_s[warp][1][o] = s1; }
    }
    __syncwarp();

    int q = -1, kk = 0;
    if (lane < 9)                     { q = 0; kk = lane; }
    else if (lane >= 16 && lane < 25) { q = 1; kk = lane - 16; }

    if (q >= 0) {
        float o1v = wi_s[warp][q][kk]      + __ldg(b_off + kk);
        float o2v = wi_s[warp][q][9 + kk]  + __ldg(b_off + 9 + kk);
        float mlg = wi_s[warp][q][18 + kk] + __ldg(b_off + 18 + kk);
        float mv  = 1.f / (1.f + __expf(-mlg));

        float pyv = o1v + (float)(yy_[q] - 1 + kk / 3);
        float pxv = o2v + (float)(xx_[q] - 1 + kk % 3);
        float yf = floorf(pyv), xf = floorf(pxv);
        float dy = pyv - yf, dx = pxv - xf;
        int iy = (int)yf, ix = (int)xf;

        int base = b_[q] << 12;
        int yc0 = min(max(iy, 0), 63),     yc1 = min(max(iy + 1, 0), 63);
        int xc0 = min(max(ix, 0), 63),     xc1 = min(max(ix + 1, 0), 63);
        float vy0 = ((unsigned)iy       < 64u) ? 1.f : 0.f;
        float vy1 = ((unsigned)(iy + 1) < 64u) ? 1.f : 0.f;
        float vx0 = ((unsigned)ix       < 64u) ? 1.f : 0.f;
        float vx1 = ((unsigned)(ix + 1) < 64u) ? 1.f : 0.f;

        int4 mi = make_int4(((base + (yc0 << 6) + xc0) << 8),
                            ((base + (yc0 << 6) + xc1) << 8),
                            ((base + (yc1 << 6) + xc0) << 8),
                            ((base + (yc1 << 6) + xc1) << 8));
        float4 mw = make_float4((1.f - dy) * (1.f - dx) * mv * vy0 * vx0,
                                (1.f - dy) * dx         * mv * vy0 * vx1,
                                dy         * (1.f - dx) * mv * vy1 * vx0,
                                dy         * dx         * mv * vy1 * vx1);
        int gp = p0 + q;
        g_midx[kk * NPIX + gp] = mi;
        g_mw[kk * NPIX + gp]   = mw;
    }
}

// ---------------------------------------------------------------------------
// Kernel 3: bf16 mma.sync GEMM with split-precision fp32 emulation.
// CTA = 128 px x 128 f, 512 threads = 16 warps (4p x 4f), warp tile 32x32.
// K loop: 9 taps x 4 chunks of 64 channels.
// D = Ahi*Bhi + Ahi*Blo + Alo*Bhi  (lo*lo dropped, ~2^-16 error)
// ---------------------------------------------------------------------------
#define ASTRIDE 72
#define ABYTES  (128 * ASTRIDE)        // bf16 elems per buffer (9216)

__global__ __launch_bounds__(512)
void dcn_mma_kernel(const float* __restrict__ x, float* __restrict__ out) {
    extern __shared__ char smraw[];
    __nv_bfloat16* As_hi = (__nv_bfloat16*)smraw;
    __nv_bfloat16* As_lo = As_hi + ABYTES;
    __nv_bfloat16* Bs_hi = As_lo + ABYTES;
    __nv_bfloat16* Bs_lo = Bs_hi + ABYTES;
    int4*   mi_s = (int4*)(Bs_lo + ABYTES);
    float4* mw_s = (float4*)(mi_s + 128);

    const int tid  = threadIdx.x;
    const int wid  = tid >> 5;
    const int lane = tid & 31;
    const int p0   = blockIdx.x * 128;
    const int f0   = blockIdx.y * 128;
    const int pix  = tid >> 2;          // 0..127 (gather mapping)
    const int cq   = tid & 3;
    const int wp   = wid >> 2;          // warp p-block 0..3 (x32)
    const int wf   = wid & 3;           // warp f-block 0..3 (x32)

    const uint32_t a_base = smem_u32(As_hi);
    const uint32_t b_base = smem_u32(Bs_hi);
    const uint32_t AB_OFF = (uint32_t)(ABYTES * 2);    // bytes: hi->lo buffer delta = 9216*2

    // ldmatrix addresses (bytes)
    const int ar  = lane & 15;              // A row within 16
    const int ac  = (lane >> 4) << 3;       // A k-offset (0/8)
    const int br  = lane & 7;               // B n-row within 8
    const int bc  = ((lane >> 3) & 1) << 3; // B k-offset (0/8)

    float acc[2][4][4];
#pragma unroll
    for (int m = 0; m < 2; ++m)
#pragma unroll
        for (int n = 0; n < 4; ++n)
#pragma unroll
            for (int q = 0; q < 4; ++q) acc[m][n][q] = 0.f;

    for (int kk = 0; kk < 9; ++kk) {
        __syncthreads();
        if (tid < 128) {
            mi_s[tid] = g_midx[kk * NPIX + p0 + tid];
            mw_s[tid] = g_mw[kk * NPIX + p0 + tid];
        }
        __syncthreads();
        const int4   mi  = mi_s[pix];
        const float4 mwv = mw_s[pix];

        for (int cc = 0; cc < 4; ++cc) {
            __syncthreads();   // previous mma stage done before overwriting smem

            // ---- gather + bilinear + split into hi/lo bf16 ----
#pragma unroll
            for (int j = 0; j < 4; ++j) {
                const int cl = cq * 16 + j * 4;        // 0..63 within chunk
                const int c  = cc * 64 + cl;
                float4 v00 = __ldg((const float4*)(x + mi.x + c));
                float4 v01 = __ldg((const float4*)(x + mi.y + c));
                float4 v10 = __ldg((const float4*)(x + mi.z + c));
                float4 v11 = __ldg((const float4*)(x + mi.w + c));
                float s0 = v00.x * mwv.x + v01.x * mwv.y + v10.x * mwv.z + v11.x * mwv.w;
                float s1 = v00.y * mwv.x + v01.y * mwv.y + v10.y * mwv.z + v11.y * mwv.w;
                float s2 = v00.z * mwv.x + v01.z * mwv.y + v10.z * mwv.z + v11.z * mwv.w;
                float s3 = v00.w * mwv.x + v01.w * mwv.y + v10.w * mwv.z + v11.w * mwv.w;

                __nv_bfloat16 h0 = __float2bfloat16(s0), h1 = __float2bfloat16(s1);
                __nv_bfloat16 h2 = __float2bfloat16(s2), h3 = __float2bfloat16(s3);
                __nv_bfloat16 l0 = __float2bfloat16(s0 - __bfloat162float(h0));
                __nv_bfloat16 l1 = __float2bfloat16(s1 - __bfloat162float(h1));
                __nv_bfloat16 l2 = __float2bfloat16(s2 - __bfloat162float(h2));
                __nv_bfloat16 l3 = __float2bfloat16(s3 - __bfloat162float(h3));

                uint32_t hp0 = (uint32_t)__bfloat16_as_ushort(h0) | ((uint32_t)__bfloat16_as_ushort(h1) << 16);
                uint32_t hp1 = (uint32_t)__bfloat16_as_ushort(h2) | ((uint32_t)__bfloat16_as_ushort(h3) << 16);
                uint32_t lp0 = (uint32_t)__bfloat16_as_ushort(l0) | ((uint32_t)__bfloat16_as_ushort(l1) << 16);
                uint32_t lp1 = (uint32_t)__bfloat16_as_ushort(l2) | ((uint32_t)__bfloat16_as_ushort(l3) << 16);

                *(uint2*)(As_hi + pix * ASTRIDE + cl) = make_uint2(hp0, hp1);
                *(uint2*)(As_lo + pix * ASTRIDE + cl) = make_uint2(lp0, lp1);
            }

            // ---- copy B chunk (hi/lo, [128][72] bf16 = 1152 float4 each) ----
            {
                const int blk = (kk * 4 + cc) * 2 + blockIdx.y;
                const float4* srch = (const float4*)(g_wbhi + blk * ABYTES);
                const float4* srcl = (const float4*)(g_wblo + blk * ABYTES);
                float4* dsth = (float4*)Bs_hi;
                float4* dstl = (float4*)Bs_lo;
#pragma unroll
                for (int i2 = 0; i2 < 2; ++i2) {
                    dsth[tid + i2 * 512] = srch[tid + i2 * 512];
                    dstl[tid + i2 * 512] = srcl[tid + i2 * 512];
                }
                if (tid < 128) {
                    dsth[tid + 1024] = srch[tid + 1024];
                    dstl[tid + 1024] = srcl[tid + 1024];
                }
            }
            __syncthreads();

            // ---- mma stage: 4 k16-steps ----
#pragma unroll
            for (int ko = 0; ko < 4; ++ko) {
                const int k0 = ko * 16;
                // A fragments (hi, lo) for 2 m-tiles
                uint32_t ah[2][4], al[2][4];
#pragma unroll
                for (int m = 0; m < 2; ++m) {
                    uint32_t aaddr = a_base +
                        (uint32_t)(((wp * 32 + m * 16 + ar) * ASTRIDE + k0 + ac) * 2);
                    asm volatile("ldmatrix.sync.aligned.m8n8.x4.shared.b16 {%0,%1,%2,%3}, [%4];"
                        : "=r"(ah[m][0]), "=r"(ah[m][1]), "=r"(ah[m][2]), "=r"(ah[m][3])
                        : "r"(aaddr));
                    asm volatile("ldmatrix.sync.aligned.m8n8.x4.shared.b16 {%0,%1,%2,%3}, [%4];"
                        : "=r"(al[m][0]), "=r"(al[m][1]), "=r"(al[m][2]), "=r"(al[m][3])
                        : "r"(aaddr + AB_OFF));
                }
                // B fragments (hi, lo) for 4 n-tiles
                uint32_t bh[4][2], bl[4][2];
#pragma unroll
                for (int n = 0; n < 4; ++n) {
                    uint32_t baddr = b_base +
                        (uint32_t)(((wf * 32 + n * 8 + br) * ASTRIDE + k0 + bc) * 2);
                    asm volatile("ldmatrix.sync.aligned.m8n8.x2.shared.b16 {%0,%1}, [%2];"
                        : "=r"(bh[n][0]), "=r"(bh[n][1]) : "r"(baddr));
                    asm volatile("ldmatrix.sync.aligned.m8n8.x2.shared.b16 {%0,%1}, [%2];"
                        : "=r"(bl[n][0]), "=r"(bl[n][1]) : "r"(baddr + AB_OFF));
                }
#pragma unroll
                for (int m = 0; m < 2; ++m)
#pragma unroll
                    for (int n = 0; n < 4; ++n) {
                        float* c = acc[m][n];
#define MMA(A0,A1,A2,A3,B0,B1) \
    asm volatile("mma.sync.aligned.m16n8k16.row.col.f32.bf16.bf16.f32 " \
        "{%0,%1,%2,%3}, {%4,%5,%6,%7}, {%8,%9}, {%0,%1,%2,%3};" \
        : "+f"(c[0]), "+f"(c[1]), "+f"(c[2]), "+f"(c[3]) \
        : "r"(A0), "r"(A1), "r"(A2), "r"(A3), "r"(B0), "r"(B1))
                        MMA(ah[m][0], ah[m][1], ah[m][2], ah[m][3], bh[n][0], bh[n][1]);
                        MMA(ah[m][0], ah[m][1], ah[m][2], ah[m][3], bl[n][0], bl[n][1]);
                        MMA(al[m][0], al[m][1], al[m][2], al[m][3], bh[n][0], bh[n][1]);
#undef MMA
                    }
            }
        }
    }

    // ---- epilogue: fragments -> out ----
#pragma unroll
    for (int m = 0; m < 2; ++m) {
        const int r0 = p0 + wp * 32 + m * 16 + (lane >> 2);
#pragma unroll
        for (int n = 0; n < 4; ++n) {
            const int col = f0 + wf * 32 + n * 8 + (lane & 3) * 2;
            *(float2*)(out + r0 * 256 + col)       = make_float2(acc[m][n][0], acc[m][n][1]);
            *(float2*)(out + (r0 + 8) * 256 + col) = make_float2(acc[m][n][2], acc[m][n][3]);
        }
    }
}

// ---------------------------------------------------------------------------
extern "C" void kernel_launch(void* const* d_in, const int* in_sizes, int n_in,
                              void* d_out, int out_size) {
    const float* x     = (const float*)d_in[0];   // [4,64,64,256]
    const float* w_off = (const float*)d_in[1];   // [3,3,256,27]
    const float* b_off = (const float*)d_in[2];   // [27]
    const float* filt  = (const float*)d_in[3];   // [256,256,3,3]
    float* out = (float*)d_out;                   // [4,64,64,256]

    const int smem = 4 * ABYTES * 2 + 128 * 16 + 128 * 16 + 256;  // ~78KB
    cudaFuncSetAttribute(dcn_mma_kernel, cudaFuncAttributeMaxDynamicSharedMemorySize, smem);

    split_filt_kernel<<<2304, 256>>>(filt);
    offset_meta_kernel<<<1024, 256>>>(x, w_off, b_off);
    dcn_mma_kernel<<<dim3(128, 2), 512, smem>>>(x, out);
}

// round 4
// speedup vs baseline: 2.0245x; 1.0997x over previous
#include <cuda_runtime.h>
#include <cuda_bf16.h>
#include <cstdint>

// Problem constants
#define NPIX 16384         // B*H*W = 4*64*64
#define KK9 9

// Scratch (allocation-free: __device__ globals)
__device__ int4   g_midx[KK9 * NPIX];        // corner element offsets (pre-multiplied by C)
__device__ float4 g_mw[KK9 * NPIX];          // bilinear*mask*valid weights
// B operand, split bf16 hi/lo, layout [kk][cc(4)][fb(2)] blocks of [128 f][72 ch] (pad 64->72)
__device__ __nv_bfloat16 g_wbhi[KK9 * 4 * 2 * 128 * 72];
__device__ __nv_bfloat16 g_wblo[KK9 * 4 * 2 * 128 * 72];

__device__ __forceinline__ uint32_t smem_u32(const void* p) {
    uint32_t a;
    asm("{ .reg .u64 t; cvta.to.shared.u64 t, %1; cvt.u32.u64 %0, t; }" : "=r"(a) : "l"(p));
    return a;
}
#define CP_ASYNC16(dst_u32, src_ptr) \
    asm volatile("cp.async.cg.shared.global [%0], [%1], 16;" :: "r"(dst_u32), "l"(src_ptr))
#define CP_COMMIT()  asm volatile("cp.async.commit_group;" ::: "memory")
#define CP_WAIT1()   asm volatile("cp.async.wait_group 1;" ::: "memory")
#define CP_WAIT0()   asm volatile("cp.async.wait_group 0;" ::: "memory")

// ---------------------------------------------------------------------------
// Kernel 1: split filt [F,C,3,3] -> bf16 hi/lo in [blk][f(128)][72] layout
// c is the fast index per thread-block -> coalesced writes, stride-36B reads.
// ---------------------------------------------------------------------------
__global__ void split_filt_kernel(const float* __restrict__ filt) {
    int i = blockIdx.x * 256 + threadIdx.x;    // 9*256*256
    int c  = i & 255;
    int f  = (i >> 8) & 255;
    int kk = i >> 16;
    float w = filt[(f * 256 + c) * 9 + kk];
    __nv_bfloat16 hi = __float2bfloat16(w);
    __nv_bfloat16 lo = __float2bfloat16(w - __bfloat162float(hi));
    int cc = c >> 6, col = c & 63, fb = f >> 7, row = f & 127;
    int blk = (kk * 4 + cc) * 2 + fb;
    int idx = blk * (128 * 72) + row * 72 + col;
    g_wbhi[idx] = hi;
    g_wblo[idx] = lo;
}

// ---------------------------------------------------------------------------
// Kernel 2: offset conv (3x3, C->27, SAME) + sampling metadata (proven R1)
// ---------------------------------------------------------------------------
__global__ __launch_bounds__(256) void offset_meta_kernel(
    const float* __restrict__ x, const float* __restrict__ w_off,
    const float* __restrict__ b_off) {
    __shared__ float ws[9 * 32 * 29];
    __shared__ float wi_s[8][2][27];

    const int tid  = threadIdx.x;
    const int warp = tid >> 5;
    const int lane = tid & 31;
    const int p0   = blockIdx.x * 16 + warp * 2;

    int b_[2], yy_[2], xx_[2];
#pragma unroll
    for (int q = 0; q < 2; ++q) {
        int gp = p0 + q;
        b_[q]  = gp >> 12;
        int r  = gp & 4095;
        yy_[q] = r >> 6;
        xx_[q] = r & 63;
    }

    float acc0[27], acc1[27];
#pragma unroll
    for (int o = 0; o < 27; ++o) { acc0[o] = 0.f; acc1[o] = 0.f; }

    for (int cc = 0; cc < 8; ++cc) {
        __syncthreads();
        for (int i = tid; i < 9 * 32 * 27; i += 256) {
            int tap = i / 864;
            int r   = i - tap * 864;
            int cl  = r / 27;
            int o   = r - cl * 27;
            ws[(tap * 32 + cl) * 29 + o] = w_off[(tap * 256 + cc * 32 + cl) * 27 + o];
        }
        __syncthreads();

        const int c = cc * 32 + lane;
#pragma unroll
        for (int tap = 0; tap < 9; ++tap) {
            const int ki = tap / 3, kj = tap % 3;
            float xv0, xv1;
            {
                int yy = yy_[0] - 1 + ki, xc = xx_[0] - 1 + kj;
                xv0 = ((unsigned)yy < 64u && (unsigned)xc < 64u)
                          ? __ldg(x + (((b_[0] << 12) + (yy << 6) + xc) << 8) + c) : 0.f;
            }
            {
                int yy = yy_[1] - 1 + ki, xc = xx_[1] - 1 + kj;
                xv1 = ((unsigned)yy < 64u && (unsigned)xc < 64u)
                          ? __ldg(x + (((b_[1] << 12) + (yy << 6) + xc) << 8) + c) : 0.f;
            }
            const float* wrow = &ws[(tap * 32 + lane) * 29];
#pragma unroll
            for (int o = 0; o < 27; ++o) {
                float wv = wrow[o];
                acc0[o] += wv * xv0;
                acc1[o] += wv * xv1;
            }
        }
    }

#pragma unroll
    for (int o = 0; o < 27; ++o) {
        float s0 = acc0[o], s1 = acc1[o];
#pragma unroll
        for (int sft = 16; sft; sft >>= 1) {
            s0 += __shfl_xor_sync(0xffffffffu, s0, sft);
            s1 += __shfl_xor_sync(0xffffffffu, s1, sft);
        }
        if (lane == 0) { wi_s[warp][0][o] = s0; wi_s[warp][1][o] = s1; }
    }
    __syncwarp();

    int q = -1, kk = 0;
    if (lane < 9)                     { q = 0; kk = lane; }
    else if (lane >= 16 && lane < 25) { q = 1; kk = lane - 16; }

    if (q >= 0) {
        float o1v = wi_s[warp][q][kk]      + __ldg(b_off + kk);
        float o2v = wi_s[warp][q][9 + kk]  + __ldg(b_off + 9 + kk);
        float mlg = wi_s[warp][q][18 + kk] + __ldg(b_off + 18 + kk);
        float mv  = 1.f / (1.f + __expf(-mlg));

        float pyv = o1v + (float)(yy_[q] - 1 + kk / 3);
        float pxv = o2v + (float)(xx_[q] - 1 + kk % 3);
        float yf = floorf(pyv), xf = floorf(pxv);
        float dy = pyv - yf, dx = pxv - xf;
        int iy = (int)yf, ix = (int)xf;

        int base = b_[q] << 12;
        int yc0 = min(max(iy, 0), 63),     yc1 = min(max(iy + 1, 0), 63);
        int xc0 = min(max(ix, 0), 63),     xc1 = min(max(ix + 1, 0), 63);
        float vy0 = ((unsigned)iy       < 64u) ? 1.f : 0.f;
        float vy1 = ((unsigned)(iy + 1) < 64u) ? 1.f : 0.f;
        float vx0 = ((unsigned)ix       < 64u) ? 1.f : 0.f;
        float vx1 = ((unsigned)(ix + 1) < 64u) ? 1.f : 0.f;

        int4 mi = make_int4(((base + (yc0 << 6) + xc0) << 8),
                            ((base + (yc0 << 6) + xc1) << 8),
                            ((base + (yc1 << 6) + xc0) << 8),
                            ((base + (yc1 << 6) + xc1) << 8));
        float4 mw = make_float4((1.f - dy) * (1.f - dx) * mv * vy0 * vx0,
                                (1.f - dy) * dx         * mv * vy0 * vx1,
                                dy         * (1.f - dx) * mv * vy1 * vx0,
                                dy         * dx         * mv * vy1 * vx1);
        int gp = p0 + q;
        g_midx[kk * NPIX + gp] = mi;
        g_mw[kk * NPIX + gp]   = mw;
    }
}

// ---------------------------------------------------------------------------
// Kernel 3: bf16 mma.sync GEMM with split-precision fp32 emulation.
// CTA = 64 px x 128 f, 256 threads = 8 warps (2p x 4f), warp tile 32x32.
// 2 CTAs/SM for cross-CTA latency hiding; cp.async double-buffered B.
// D = Ahi*Bhi + Ahi*Blo + Alo*Bhi  (lo*lo dropped, ~2^-16 error)
// ---------------------------------------------------------------------------
#define ASTRIDE 72
#define A_ELEMS (64 * ASTRIDE)         // 4608 bf16 per A buffer
#define B_ELEMS (128 * ASTRIDE)        // 9216 bf16 per B buffer
#define A_LO_BYTES (A_ELEMS * 2)       // 9216
#define B_LO_BYTES (B_ELEMS * 2)       // 18432
// smem bf16-element offsets
#define OFF_AHI  0
#define OFF_ALO  A_ELEMS
#define OFF_B(buf) (2 * A_ELEMS + (buf) * 2 * B_ELEMS)
#define OFF_META (2 * A_ELEMS + 4 * B_ELEMS)             // bytes follow below
#define SMEM_BYTES ((2 * A_ELEMS + 4 * B_ELEMS) * 2 + 576 * 16 + 576 * 16)

__global__ __launch_bounds__(256, 2)
void dcn_mma_kernel(const float* __restrict__ x, float* __restrict__ out) {
    extern __shared__ char smraw[];
    __nv_bfloat16* smb  = (__nv_bfloat16*)smraw;
    __nv_bfloat16* As_hi = smb + OFF_AHI;
    int4*   mi_all = (int4*)(smb + OFF_META);
    float4* mw_all = (float4*)(mi_all + 576);

    const int tid  = threadIdx.x;
    const int wid  = tid >> 5;
    const int lane = tid & 31;
    const int p0   = blockIdx.x * 64;
    const int f0   = blockIdx.y * 128;
    const int pix  = tid >> 2;          // 0..63 (gather mapping)
    const int cq   = tid & 3;
    const int wp   = wid >> 2;          // warp p-block 0..1 (x32)
    const int wf   = wid & 3;           // warp f-block 0..3 (x32)

    const uint32_t a_base = smem_u32(As_hi);
    const uint32_t b_base0 = smem_u32(smb + OFF_B(0));

    // ---- preload all taps' metadata for this pixel tile ----
    for (int i = tid; i < 576; i += 256) {
        int kk = i >> 6, pp = i & 63;
        mi_all[i] = g_midx[kk * NPIX + p0 + pp];
        mw_all[i] = g_mw[kk * NPIX + p0 + pp];
    }
    __syncthreads();

    // ldmatrix lane addressing
    const int ar  = lane & 15;
    const int ac  = (lane >> 4) << 3;
    const int br  = lane & 7;
    const int bc  = ((lane >> 3) & 1) << 3;

    float acc[2][4][4];
#pragma unroll
    for (int m = 0; m < 2; ++m)
#pragma unroll
        for (int n = 0; n < 4; ++n)
#pragma unroll
            for (int q = 0; q < 4; ++q) acc[m][n][q] = 0.f;

    // ---- B async copy helper (as a lambda-free macro-ish block) ----
    // stage s: blk = s*2 + blockIdx.y ; dst buf = which
#define COPY_B_ASYNC(s, buf) do {                                              \
        const int _blk = (s) * 2 + blockIdx.y;                                 \
        const char* _sh = (const char*)(g_wbhi + _blk * B_ELEMS);              \
        const char* _sl = (const char*)(g_wblo + _blk * B_ELEMS);              \
        uint32_t _dh = b_base0 + (uint32_t)((buf) * 2 * B_ELEMS * 2);          \
        uint32_t _dl = _dh + (uint32_t)B_LO_BYTES;                             \
        _Pragma("unroll")                                                      \
        for (int _i = 0; _i < 4; ++_i) {                                       \
            int _o = (tid + _i * 256) * 16;                                    \
            CP_ASYNC16(_dh + _o, _sh + _o);                                    \
            CP_ASYNC16(_dl + _o, _sl + _o);                                    \
        }                                                                      \
        if (tid < 128) {                                                       \
            int _o = (tid + 1024) * 16;                                        \
            CP_ASYNC16(_dh + _o, _sh + _o);                                    \
            CP_ASYNC16(_dl + _o, _sl + _o);                                    \
        }                                                                      \
    } while (0)

    COPY_B_ASYNC(0, 0);
    CP_COMMIT();

    for (int s = 0; s < 36; ++s) {
        const int kk = s >> 2, cc = s & 3;
        const int4   mi  = mi_all[kk * 64 + pix];
        const float4 mwv = mw_all[kk * 64 + pix];

        // ---- gather corners into registers (LDGs in flight across the sync) ----
        float4 v00[4], v01[4], v10[4], v11[4];
#pragma unroll
        for (int j = 0; j < 4; ++j) {
            const int c = cc * 64 + cq * 16 + j * 4;
            v00[j] = __ldg((const float4*)(x + mi.x + c));
            v01[j] = __ldg((const float4*)(x + mi.y + c));
            v10[j] = __ldg((const float4*)(x + mi.z + c));
            v11[j] = __ldg((const float4*)(x + mi.w + c));
        }

        __syncthreads();                 // MMA(s-1) done: A smem + B buf[(s+1)&1] free

        if (s + 1 < 36) { COPY_B_ASYNC(s + 1, (s + 1) & 1); }
        CP_COMMIT();                     // commit (possibly empty) group each stage

        // ---- bilinear + split + store A ----
#pragma unroll
        for (int j = 0; j < 4; ++j) {
            const int cl = cq * 16 + j * 4;
            float s0 = v00[j].x * mwv.x + v01[j].x * mwv.y + v10[j].x * mwv.z + v11[j].x * mwv.w;
            float s1 = v00[j].y * mwv.x + v01[j].y * mwv.y + v10[j].y * mwv.z + v11[j].y * mwv.w;
            float s2 = v00[j].z * mwv.x + v01[j].z * mwv.y + v10[j].z * mwv.z + v11[j].z * mwv.w;
            float s3 = v00[j].w * mwv.x + v01[j].w * mwv.y + v10[j].w * mwv.z + v11[j].w * mwv.w;

            __nv_bfloat16 h0 = __float2bfloat16(s0), h1 = __float2bfloat16(s1);
            __nv_bfloat16 h2 = __float2bfloat16(s2), h3 = __float2bfloat16(s3);
            __nv_bfloat16 l0 = __float2bfloat16(s0 - __bfloat162float(h0));
            __nv_bfloat16 l1 = __float2bfloat16(s1 - __bfloat162float(h1));
            __nv_bfloat16 l2 = __float2bfloat16(s2 - __bfloat162float(h2));
            __nv_bfloat16 l3 = __float2bfloat16(s3 - __bfloat162float(h3));

            uint32_t hp0 = (uint32_t)__bfloat16_as_ushort(h0) | ((uint32_t)__bfloat16_as_ushort(h1) << 16);
            uint32_t hp1 = (uint32_t)__bfloat16_as_ushort(h2) | ((uint32_t)__bfloat16_as_ushort(h3) << 16);
            uint32_t lp0 = (uint32_t)__bfloat16_as_ushort(l0) | ((uint32_t)__bfloat16_as_ushort(l1) << 16);
            uint32_t lp1 = (uint32_t)__bfloat16_as_ushort(l2) | ((uint32_t)__bfloat16_as_ushort(l3) << 16);

            *(uint2*)(smb + OFF_AHI + pix * ASTRIDE + cl) = make_uint2(hp0, hp1);
            *(uint2*)(smb + OFF_ALO + pix * ASTRIDE + cl) = make_uint2(lp0, lp1);
        }

        CP_WAIT1();                      // B(s) landed (only the s+1 group may remain)
        __syncthreads();

        // ---- mma stage: 4 k16-steps on B buf[s&1] ----
        const uint32_t b_stage = b_base0 + (uint32_t)((s & 1) * 2 * B_ELEMS * 2);
#pragma unroll
        for (int ko = 0; ko < 4; ++ko) {
            const int k0 = ko * 16;
            uint32_t ah[2][4], al[2][4];
#pragma unroll
            for (int m = 0; m < 2; ++m) {
                uint32_t aaddr = a_base +
                    (uint32_t)(((wp * 32 + m * 16 + ar) * ASTRIDE + k0 + ac) * 2);
                asm volatile("ldmatrix.sync.aligned.m8n8.x4.shared.b16 {%0,%1,%2,%3}, [%4];"
                    : "=r"(ah[m][0]), "=r"(ah[m][1]), "=r"(ah[m][2]), "=r"(ah[m][3])
                    : "r"(aaddr));
                asm volatile("ldmatrix.sync.aligned.m8n8.x4.shared.b16 {%0,%1,%2,%3}, [%4];"
                    : "=r"(al[m][0]), "=r"(al[m][1]), "=r"(al[m][2]), "=r"(al[m][3])
                    : "r"(aaddr + (uint32_t)A_LO_BYTES));
            }
            uint32_t bh[4][2], bl[4][2];
#pragma unroll
            for (int n = 0; n < 4; ++n) {
                uint32_t baddr = b_stage +
                    (uint32_t)(((wf * 32 + n * 8 + br) * ASTRIDE + k0 + bc) * 2);
                asm volatile("ldmatrix.sync.aligned.m8n8.x2.shared.b16 {%0,%1}, [%2];"
                    : "=r"(bh[n][0]), "=r"(bh[n][1]) : "r"(baddr));
                asm volatile("ldmatrix.sync.aligned.m8n8.x2.shared.b16 {%0,%1}, [%2];"
                    : "=r"(bl[n][0]), "=r"(bl[n][1]) : "r"(baddr + (uint32_t)B_LO_BYTES));
            }
#pragma unroll
            for (int m = 0; m < 2; ++m)
#pragma unroll
                for (int n = 0; n < 4; ++n) {
                    float* c = acc[m][n];
#define MMA(A0,A1,A2,A3,B0,B1) \
    asm volatile("mma.sync.aligned.m16n8k16.row.col.f32.bf16.bf16.f32 " \
        "{%0,%1,%2,%3}, {%4,%5,%6,%7}, {%8,%9}, {%0,%1,%2,%3};" \
        : "+f"(c[0]), "+f"(c[1]), "+f"(c[2]), "+f"(c[3]) \
        : "r"(A0), "r"(A1), "r"(A2), "r"(A3), "r"(B0), "r"(B1))
                    MMA(ah[m][0], ah[m][1], ah[m][2], ah[m][3], bh[n][0], bh[n][1]);
                    MMA(ah[m][0], ah[m][1], ah[m][2], ah[m][3], bl[n][0], bl[n][1]);
                    MMA(al[m][0], al[m][1], al[m][2], al[m][3], bh[n][0], bh[n][1]);
#undef MMA
                }
        }
    }

    CP_WAIT0();

    // ---- epilogue: fragments -> out ----
#pragma unroll
    for (int m = 0; m < 2; ++m) {
        const int r0 = p0 + wp * 32 + m * 16 + (lane >> 2);
#pragma unroll
        for (int n = 0; n < 4; ++n) {
            const int col = f0 + wf * 32 + n * 8 + (lane & 3) * 2;
            *(float2*)(out + r0 * 256 + col)       = make_float2(acc[m][n][0], acc[m][n][1]);
            *(float2*)(out + (r0 + 8) * 256 + col) = make_float2(acc[m][n][2], acc[m][n][3]);
        }
    }
}

// ---------------------------------------------------------------------------
extern "C" void kernel_launch(void* const* d_in, const int* in_sizes, int n_in,
                              void* d_out, int out_size) {
    const float* x     = (const float*)d_in[0];   // [4,64,64,256]
    const float* w_off = (const float*)d_in[1];   // [3,3,256,27]
    const float* b_off = (const float*)d_in[2];   // [27]
    const float* filt  = (const float*)d_in[3];   // [256,256,3,3]
    float* out = (float*)d_out;                   // [4,64,64,256]

    cudaFuncSetAttribute(dcn_mma_kernel, cudaFuncAttributeMaxDynamicSharedMemorySize, SMEM_BYTES);

    split_filt_kernel<<<2304, 256>>>(filt);
    offset_meta_kernel<<<1024, 256>>>(x, w_off, b_off);
    dcn_mma_kernel<<<dim3(256, 2), 256, SMEM_BYTES>>>(x, out);
}

// round 5
// speedup vs baseline: 2.0564x; 1.0157x over previous
#include <cuda_runtime.h>
#include <cuda_bf16.h>
#include <cstdint>

// Problem constants
#define NPIX   16384       // B*H*W = 4*64*64
#define KSTEPS 72          // 9 taps * 8 k32-steps

// Scratch (allocation-free: __device__ globals)
__device__ int4   g_midx[9 * NPIX];          // corner element offsets (pre-multiplied by C)
__device__ float4 g_mw[9 * NPIX];            // bilinear*mask*valid weights
// B operand, split bf16 hi/lo: [kstep][f(256)][ch(32)]
__device__ __nv_bfloat16 g_wbhi[KSTEPS * 256 * 32];
__device__ __nv_bfloat16 g_wblo[KSTEPS * 256 * 32];
// Staged A (im2col output), split bf16 hi/lo: [kstep][px(16384)][ch(32)]  (75.5 MB each)
__device__ __nv_bfloat16 g_Ahi[KSTEPS * NPIX * 32];
__device__ __nv_bfloat16 g_Alo[KSTEPS * NPIX * 32];

__device__ __forceinline__ uint32_t smem_u32(const void* p) {
    uint32_t a;
    asm("{ .reg .u64 t; cvta.to.shared.u64 t, %1; cvt.u32.u64 %0, t; }" : "=r"(a) : "l"(p));
    return a;
}
#define CP_ASYNC16(dst_u32, src_ptr) \
    asm volatile("cp.async.cg.shared.global [%0], [%1], 16;" :: "r"(dst_u32), "l"(src_ptr))
#define CP_COMMIT()  asm volatile("cp.async.commit_group;" ::: "memory")
#define CP_WAIT3()   asm volatile("cp.async.wait_group 3;" ::: "memory")

// ---------------------------------------------------------------------------
// Kernel 1: split filt [F,C,3,3] -> bf16 hi/lo in [kstep][f][32] layout
// ---------------------------------------------------------------------------
__global__ void split_filt_kernel(const float* __restrict__ filt) {
    int i = blockIdx.x * 256 + threadIdx.x;    // 9*256*256
    int c  = i & 255;
    int f  = (i >> 8) & 255;
    int kk = i >> 16;
    float w = filt[(f * 256 + c) * 9 + kk];
    __nv_bfloat16 hi = __float2bfloat16(w);
    __nv_bfloat16 lo = __float2bfloat16(w - __bfloat162float(hi));
    int kstep = kk * 8 + (c >> 5);
    int ch    = c & 31;
    int idx   = (kstep * 256 + f) * 32 + ch;
    g_wbhi[idx] = hi;
    g_wblo[idx] = lo;
}

// ---------------------------------------------------------------------------
// Kernel 2: offset conv (3x3, C->27, SAME) + sampling metadata (proven R1)
// ---------------------------------------------------------------------------
__global__ __launch_bounds__(256) void offset_meta_kernel(
    const float* __restrict__ x, const float* __restrict__ w_off,
    const float* __restrict__ b_off) {
    __shared__ float ws[9 * 32 * 29];
    __shared__ float wi_s[8][2][27];

    const int tid  = threadIdx.x;
    const int warp = tid >> 5;
    const int lane = tid & 31;
    const int p0   = blockIdx.x * 16 + warp * 2;

    int b_[2], yy_[2], xx_[2];
#pragma unroll
    for (int q = 0; q < 2; ++q) {
        int gp = p0 + q;
        b_[q]  = gp >> 12;
        int r  = gp & 4095;
        yy_[q] = r >> 6;
        xx_[q] = r & 63;
    }

    float acc0[27], acc1[27];
#pragma unroll
    for (int o = 0; o < 27; ++o) { acc0[o] = 0.f; acc1[o] = 0.f; }

    for (int cc = 0; cc < 8; ++cc) {
        __syncthreads();
        for (int i = tid; i < 9 * 32 * 27; i += 256) {
            int tap = i / 864;
            int r   = i - tap * 864;
            int cl  = r / 27;
            int o   = r - cl * 27;
            ws[(tap * 32 + cl) * 29 + o] = w_off[(tap * 256 + cc * 32 + cl) * 27 + o];
        }
        __syncthreads();

        const int c = cc * 32 + lane;
#pragma unroll
        for (int tap = 0; tap < 9; ++tap) {
            const int ki = tap / 3, kj = tap % 3;
            float xv0, xv1;
            {
                int yy = yy_[0] - 1 + ki, xc = xx_[0] - 1 + kj;
                xv0 = ((unsigned)yy < 64u && (unsigned)xc < 64u)
                          ? __ldg(x + (((b_[0] << 12) + (yy << 6) + xc) << 8) + c) : 0.f;
            }
            {
                int yy = yy_[1] - 1 + ki, xc = xx_[1] - 1 + kj;
                xv1 = ((unsigned)yy < 64u && (unsigned)xc < 64u)
                          ? __ldg(x + (((b_[1] << 12) + (yy << 6) + xc) << 8) + c) : 0.f;
            }
            const float* wrow = &ws[(tap * 32 + lane) * 29];
#pragma unroll
            for (int o = 0; o < 27; ++o) {
                float wv = wrow[o];
                acc0[o] += wv * xv0;
                acc1[o] += wv * xv1;
            }
        }
    }

#pragma unroll
    for (int o = 0; o < 27; ++o) {
        float s0 = acc0[o], s1 = acc1[o];
#pragma unroll
        for (int sft = 16; sft; sft >>= 1) {
            s0 += __shfl_xor_sync(0xffffffffu, s0, sft);
            s1 += __shfl_xor_sync(0xffffffffu, s1, sft);
        }
        if (lane == 0) { wi_s[warp][0][o] = s0; wi_s[warp][1][o] = s1; }
    }
    __syncwarp();

    int q = -1, kk = 0;
    if (lane < 9)                     { q = 0; kk = lane; }
    else if (lane >= 16 && lane < 25) { q = 1; kk = lane - 16; }

    if (q >= 0) {
        float o1v = wi_s[warp][q][kk]      + __ldg(b_off + kk);
        float o2v = wi_s[warp][q][9 + kk]  + __ldg(b_off + 9 + kk);
        float mlg = wi_s[warp][q][18 + kk] + __ldg(b_off + 18 + kk);
        float mv  = 1.f / (1.f + __expf(-mlg));

        float pyv = o1v + (float)(yy_[q] - 1 + kk / 3);
        float pxv = o2v + (float)(xx_[q] - 1 + kk % 3);
        float yf = floorf(pyv), xf = floorf(pxv);
        float dy = pyv - yf, dx = pxv - xf;
        int iy = (int)yf, ix = (int)xf;

        int base = b_[q] << 12;
        int yc0 = min(max(iy, 0), 63),     yc1 = min(max(iy + 1, 0), 63);
        int xc0 = min(max(ix, 0), 63),     xc1 = min(max(ix + 1, 0), 63);
        float vy0 = ((unsigned)iy       < 64u) ? 1.f : 0.f;
        float vy1 = ((unsigned)(iy + 1) < 64u) ? 1.f : 0.f;
        float vx0 = ((unsigned)ix       < 64u) ? 1.f : 0.f;
        float vx1 = ((unsigned)(ix + 1) < 64u) ? 1.f : 0.f;

        int4 mi = make_int4(((base + (yc0 << 6) + xc0) << 8),
                            ((base + (yc0 << 6) + xc1) << 8),
                            ((base + (yc1 << 6) + xc0) << 8),
                            ((base + (yc1 << 6) + xc1) << 8));
        float4 mw = make_float4((1.f - dy) * (1.f - dx) * mv * vy0 * vx0,
                                (1.f - dy) * dx         * mv * vy0 * vx1,
                                dy         * (1.f - dx) * mv * vy1 * vx0,
                                dy         * dx         * mv * vy1 * vx1);
        int gp = p0 + q;
        g_midx[kk * NPIX + gp] = mi;
        g_mw[kk * NPIX + gp]   = mw;
    }
}

// ---------------------------------------------------------------------------
// Kernel 3: im2col — gather + bilinear + hi/lo split, ONCE per pixel.
// block = (64 px) x (stage s = kk*4+cc); thread = (px, 16-ch quad).
// Output: g_Ahi/g_Alo [kstep][px][32].
// ---------------------------------------------------------------------------
__global__ __launch_bounds__(256) void im2col_kernel(const float* __restrict__ x) {
    const int tid  = threadIdx.x;
    const int pxl  = tid >> 2;
    const int cq   = tid & 3;
    const int px   = blockIdx.x * 64 + pxl;
    const int s    = blockIdx.y;           // 0..35
    const int kk   = s >> 2, cc = s & 3;

    const int4   mi = __ldg(&g_midx[kk * NPIX + px]);
    const float4 mw = __ldg(&g_mw[kk * NPIX + px]);

    uint2 ho[4], lo_[4];
#pragma unroll
    for (int j = 0; j < 4; ++j) {
        const int c = cc * 64 + cq * 16 + j * 4;
        float4 v00 = __ldg((const float4*)(x + mi.x + c));
        float4 v01 = __ldg((const float4*)(x + mi.y + c));
        float4 v10 = __ldg((const float4*)(x + mi.z + c));
        float4 v11 = __ldg((const float4*)(x + mi.w + c));
        float s0 = v00.x * mw.x + v01.x * mw.y + v10.x * mw.z + v11.x * mw.w;
        float s1 = v00.y * mw.x + v01.y * mw.y + v10.y * mw.z + v11.y * mw.w;
        float s2 = v00.z * mw.x + v01.z * mw.y + v10.z * mw.z + v11.z * mw.w;
        float s3 = v00.w * mw.x + v01.w * mw.y + v10.w * mw.z + v11.w * mw.w;

        __nv_bfloat16 h0 = __float2bfloat16(s0), h1 = __float2bfloat16(s1);
        __nv_bfloat16 h2 = __float2bfloat16(s2), h3 = __float2bfloat16(s3);
        __nv_bfloat16 l0 = __float2bfloat16(s0 - __bfloat162float(h0));
        __nv_bfloat16 l1 = __float2bfloat16(s1 - __bfloat162float(h1));
        __nv_bfloat16 l2 = __float2bfloat16(s2 - __bfloat162float(h2));
        __nv_bfloat16 l3 = __float2bfloat16(s3 - __bfloat162float(h3));

        ho[j].x  = (uint32_t)__bfloat16_as_ushort(h0) | ((uint32_t)__bfloat16_as_ushort(h1) << 16);
        ho[j].y  = (uint32_t)__bfloat16_as_ushort(h2) | ((uint32_t)__bfloat16_as_ushort(h3) << 16);
        lo_[j].x = (uint32_t)__bfloat16_as_ushort(l0) | ((uint32_t)__bfloat16_as_ushort(l1) << 16);
        lo_[j].y = (uint32_t)__bfloat16_as_ushort(l2) | ((uint32_t)__bfloat16_as_ushort(l3) << 16);
    }

    const int kstep = s * 2 + (cq >> 1);
    const int dst   = (kstep * NPIX + px) * 32 + (cq & 1) * 16;
    uint4* dh = (uint4*)(g_Ahi + dst);
    uint4* dl = (uint4*)(g_Alo + dst);
    dh[0] = make_uint4(ho[0].x, ho[0].y, ho[1].x, ho[1].y);
    dh[1] = make_uint4(ho[2].x, ho[2].y, ho[3].x, ho[3].y);
    dl[0] = make_uint4(lo_[0].x, lo_[0].y, lo_[1].x, lo_[1].y);
    dl[1] = make_uint4(lo_[2].x, lo_[2].y, lo_[3].x, lo_[3].y);
}

// ---------------------------------------------------------------------------
// Kernel 4: pure bf16 GEMM, 5-stage cp.async pipeline.
// CTA = 128 px x 128 f, 512 threads = 16 warps (4p x 4f), warp tile 32x32.
// K loop: 72 k32-steps. D = Ahi*Bhi + Ahi*Blo + Alo*Bhi.
// ---------------------------------------------------------------------------
#define PSTRIDE 40                       // padded smem row (elems) for 32-ch tiles
#define BUF_B   (128 * PSTRIDE * 2)      // 10240 bytes per (operand,precision) buffer
#define STAGE_B (4 * BUF_B)              // 40960 bytes per stage
#define NSTG    5
#define SMEM_BYTES (NSTG * STAGE_B)      // 204800

__global__ __launch_bounds__(512, 1)
void dcn_gemm_kernel(float* __restrict__ out) {
    extern __shared__ char smraw[];
    const uint32_t smb = smem_u32(smraw);

    const int tid  = threadIdx.x;
    const int wid  = tid >> 5;
    const int lane = tid & 31;
    const int p0   = blockIdx.x * 128;
    const int fb   = blockIdx.y;           // f-block 0/1
    const int f0   = fb * 128;
    const int wp   = wid >> 2;             // warp p-block 0..3
    const int wf   = wid & 3;              // warp f-block 0..3

    const int crow = tid >> 2;             // 0..127 copy row
    const int c4   = tid & 3;              // 16B chunk within 32-ch row

    // ldmatrix lane addressing
    const int ar = lane & 15;
    const int ac = (lane >> 4) << 3;
    const int br = lane & 7;
    const int bc = ((lane >> 3) & 1) << 3;

#define COPY_STAGE(ks, st) do {                                                  \
        uint32_t _d = smb + (st) * STAGE_B + crow * (PSTRIDE * 2) + c4 * 16;     \
        const char* _ah = (const char*)(g_Ahi + ((ks) * NPIX + p0 + crow) * 32 + c4 * 8); \
        const char* _al = (const char*)(g_Alo + ((ks) * NPIX + p0 + crow) * 32 + c4 * 8); \
        const char* _bh = (const char*)(g_wbhi + (((ks) * 256) + f0 + crow) * 32 + c4 * 8); \
        const char* _bl = (const char*)(g_wblo + (((ks) * 256) + f0 + crow) * 32 + c4 * 8); \
        CP_ASYNC16(_d,              _ah);                                        \
        CP_ASYNC16(_d + BUF_B,      _al);                                        \
        CP_ASYNC16(_d + 2 * BUF_B,  _bh);                                        \
        CP_ASYNC16(_d + 3 * BUF_B,  _bl);                                        \
    } while (0)

    // prologue: stages 0..3
#pragma unroll
    for (int st = 0; st < 4; ++st) { COPY_STAGE(st, st); CP_COMMIT(); }

    float acc[2][4][4];
#pragma unroll
    for (int m = 0; m < 2; ++m)
#pragma unroll
        for (int n = 0; n < 4; ++n)
#pragma unroll
            for (int q = 0; q < 4; ++q) acc[m][n][q] = 0.f;

    for (int ks = 0; ks < KSTEPS; ++ks) {
        CP_WAIT3();                    // stage ks landed (3 younger groups may pend)
        __syncthreads();               // visible to all + prev compute done

        if (ks + 4 < KSTEPS) { COPY_STAGE(ks + 4, (ks + 4) % NSTG); }
        CP_COMMIT();

        const int st = ks % NSTG;
        const uint32_t a_hi = smb + st * STAGE_B;
        const uint32_t b_hi = a_hi + 2 * BUF_B;

#pragma unroll
        for (int ko = 0; ko < 2; ++ko) {
            const int k0b = ko * 32;   // bytes: 16 elems * 2
            uint32_t ah[2][4], al[2][4];
#pragma unroll
            for (int m = 0; m < 2; ++m) {
                uint32_t aaddr = a_hi + (wp * 32 + m * 16 + ar) * (PSTRIDE * 2) + k0b + ac * 2;
                asm volatile("ldmatrix.sync.aligned.m8n8.x4.shared.b16 {%0,%1,%2,%3}, [%4];"
                    : "=r"(ah[m][0]), "=r"(ah[m][1]), "=r"(ah[m][2]), "=r"(ah[m][3])
                    : "r"(aaddr));
                asm volatile("ldmatrix.sync.aligned.m8n8.x4.shared.b16 {%0,%1,%2,%3}, [%4];"
                    : "=r"(al[m][0]), "=r"(al[m][1]), "=r"(al[m][2]), "=r"(al[m][3])
                    : "r"(aaddr + (uint32_t)BUF_B));
            }
            uint32_t bh[4][2], bl[4][2];
#pragma unroll
            for (int n = 0; n < 4; ++n) {
                uint32_t baddr = b_hi + (wf * 32 + n * 8 + br) * (PSTRIDE * 2) + k0b + bc * 2;
                asm volatile("ldmatrix.sync.aligned.m8n8.x2.shared.b16 {%0,%1}, [%2];"
                    : "=r"(bh[n][0]), "=r"(bh[n][1]) : "r"(baddr));
                asm volatile("ldmatrix.sync.aligned.m8n8.x2.shared.b16 {%0,%1}, [%2];"
                    : "=r"(bl[n][0]), "=r"(bl[n][1]) : "r"(baddr + (uint32_t)BUF_B));
            }
#pragma unroll
            for (int m = 0; m < 2; ++m)
#pragma unroll
                for (int n = 0; n < 4; ++n) {
                    float* c = acc[m][n];
#define MMA(A0,A1,A2,A3,B0,B1) \
    asm volatile("mma.sync.aligned.m16n8k16.row.col.f32.bf16.bf16.f32 " \
        "{%0,%1,%2,%3}, {%4,%5,%6,%7}, {%8,%9}, {%0,%1,%2,%3};" \
        : "+f"(c[0]), "+f"(c[1]), "+f"(c[2]), "+f"(c[3]) \
        : "r"(A0), "r"(A1), "r"(A2), "r"(A3), "r"(B0), "r"(B1))
                    MMA(ah[m][0], ah[m][1], ah[m][2], ah[m][3], bh[n][0], bh[n][1]);
                    MMA(ah[m][0], ah[m][1], ah[m][2], ah[m][3], bl[n][0], bl[n][1]);
                    MMA(al[m][0], al[m][1], al[m][2], al[m][3], bh[n][0], bh[n][1]);
#undef MMA
                }
        }
    }

    // ---- epilogue: fragments -> out ----
#pragma unroll
    for (int m = 0; m < 2; ++m) {
        const int r0 = p0 + wp * 32 + m * 16 + (lane >> 2);
#pragma unroll
        for (int n = 0; n < 4; ++n) {
            const int col = f0 + wf * 32 + n * 8 + (lane & 3) * 2;
            *(float2*)(out + r0 * 256 + col)       = make_float2(acc[m][n][0], acc[m][n][1]);
            *(float2*)(out + (r0 + 8) * 256 + col) = make_float2(acc[m][n][2], acc[m][n][3]);
        }
    }
}

// ---------------------------------------------------------------------------
extern "C" void kernel_launch(void* const* d_in, const int* in_sizes, int n_in,
                              void* d_out, int out_size) {
    const float* x     = (const float*)d_in[0];   // [4,64,64,256]
    const float* w_off = (const float*)d_in[1];   // [3,3,256,27]
    const float* b_off = (const float*)d_in[2];   // [27]
    const float* filt  = (const float*)d_in[3];   // [256,256,3,3]
    float* out = (float*)d_out;                   // [4,64,64,256]

    cudaFuncSetAttribute(dcn_gemm_kernel, cudaFuncAttributeMaxDynamicSharedMemorySize, SMEM_BYTES);

    split_filt_kernel<<<2304, 256>>>(filt);
    offset_meta_kernel<<<1024, 256>>>(x, w_off, b_off);
    im2col_kernel<<<dim3(256, 36), 256>>>(x);
    dcn_gemm_kernel<<<dim3(128, 2), 512, SMEM_BYTES>>>(out);
}

// round 6
// speedup vs baseline: 2.1188x; 1.0303x over previous
#include <cuda_runtime.h>
#include <cuda_bf16.h>
#include <cstdint>

// Problem constants
#define NPIX   16384       // B*H*W = 4*64*64
#define KSTEPS 72          // 9 taps * 8 k32-steps

// Scratch (allocation-free: __device__ globals)
__device__ int4   g_midx[9 * NPIX];          // corner element offsets (pre-multiplied by C)
__device__ float4 g_mw[9 * NPIX];            // bilinear*mask*valid weights
// B operand, split bf16 hi/lo: [kstep][f(256)][ch(32)]
__device__ __nv_bfloat16 g_wbhi[KSTEPS * 256 * 32];
__device__ __nv_bfloat16 g_wblo[KSTEPS * 256 * 32];
// Staged A (im2col output), split bf16 hi/lo: [kstep][px(16384)][ch(32)]
__device__ __nv_bfloat16 g_Ahi[KSTEPS * NPIX * 32];
__device__ __nv_bfloat16 g_Alo[KSTEPS * NPIX * 32];

__device__ __forceinline__ uint32_t smem_u32(const void* p) {
    uint32_t a;
    asm("{ .reg .u64 t; cvta.to.shared.u64 t, %1; cvt.u32.u64 %0, t; }" : "=r"(a) : "l"(p));
    return a;
}
#define CP_ASYNC16(dst_u32, src_ptr) \
    asm volatile("cp.async.cg.shared.global [%0], [%1], 16;" :: "r"(dst_u32), "l"(src_ptr))
#define CP_COMMIT()  asm volatile("cp.async.commit_group;" ::: "memory")
#define CP_WAIT1()   asm volatile("cp.async.wait_group 1;" ::: "memory")

// ---------------------------------------------------------------------------
// Kernel 1: split filt [F,C,3,3] -> bf16 hi/lo in [kstep][f][32] layout
// ---------------------------------------------------------------------------
__global__ void split_filt_kernel(const float* __restrict__ filt) {
    int i = blockIdx.x * 256 + threadIdx.x;    // 9*256*256
    int c  = i & 255;
    int f  = (i >> 8) & 255;
    int kk = i >> 16;
    float w = filt[(f * 256 + c) * 9 + kk];
    __nv_bfloat16 hi = __float2bfloat16(w);
    __nv_bfloat16 lo = __float2bfloat16(w - __bfloat162float(hi));
    int kstep = kk * 8 + (c >> 5);
    int ch    = c & 31;
    int idx   = (kstep * 256 + f) * 32 + ch;
    g_wbhi[idx] = hi;
    g_wblo[idx] = lo;
}

// ---------------------------------------------------------------------------
// Kernel 2: offset conv (3x3, C->27, SAME) + sampling metadata (proven R1)
// ---------------------------------------------------------------------------
__global__ __launch_bounds__(256) void offset_meta_kernel(
    const float* __restrict__ x, const float* __restrict__ w_off,
    const float* __restrict__ b_off) {
    __shared__ float ws[9 * 32 * 29];
    __shared__ float wi_s[8][2][27];

    const int tid  = threadIdx.x;
    const int warp = tid >> 5;
    const int lane = tid & 31;
    const int p0   = blockIdx.x * 16 + warp * 2;

    int b_[2], yy_[2], xx_[2];
#pragma unroll
    for (int q = 0; q < 2; ++q) {
        int gp = p0 + q;
        b_[q]  = gp >> 12;
        int r  = gp & 4095;
        yy_[q] = r >> 6;
        xx_[q] = r & 63;
    }

    float acc0[27], acc1[27];
#pragma unroll
    for (int o = 0; o < 27; ++o) { acc0[o] = 0.f; acc1[o] = 0.f; }

    for (int cc = 0; cc < 8; ++cc) {
        __syncthreads();
        for (int i = tid; i < 9 * 32 * 27; i += 256) {
            int tap = i / 864;
            int r   = i - tap * 864;
            int cl  = r / 27;
            int o   = r - cl * 27;
            ws[(tap * 32 + cl) * 29 + o] = w_off[(tap * 256 + cc * 32 + cl) * 27 + o];
        }
        __syncthreads();

        const int c = cc * 32 + lane;
#pragma unroll
        for (int tap = 0; tap < 9; ++tap) {
            const int ki = tap / 3, kj = tap % 3;
            float xv0, xv1;
            {
                int yy = yy_[0] - 1 + ki, xc = xx_[0] - 1 + kj;
                xv0 = ((unsigned)yy < 64u && (unsigned)xc < 64u)
                          ? __ldg(x + (((b_[0] << 12) + (yy << 6) + xc) << 8) + c) : 0.f;
            }
            {
                int yy = yy_[1] - 1 + ki, xc = xx_[1] - 1 + kj;
                xv1 = ((unsigned)yy < 64u && (unsigned)xc < 64u)
                          ? __ldg(x + (((b_[1] << 12) + (yy << 6) + xc) << 8) + c) : 0.f;
            }
            const float* wrow = &ws[(tap * 32 + lane) * 29];
#pragma unroll
            for (int o = 0; o < 27; ++o) {
                float wv = wrow[o];
                acc0[o] += wv * xv0;
                acc1[o] += wv * xv1;
            }
        }
    }

#pragma unroll
    for (int o = 0; o < 27; ++o) {
        float s0 = acc0[o], s1 = acc1[o];
#pragma unroll
        for (int sft = 16; sft; sft >>= 1) {
            s0 += __shfl_xor_sync(0xffffffffu, s0, sft);
            s1 += __shfl_xor_sync(0xffffffffu, s1, sft);
        }
        if (lane == 0) { wi_s[warp][0][o] = s0; wi_s[warp][1][o] = s1; }
    }
    __syncwarp();

    int q = -1, kk = 0;
    if (lane < 9)                     { q = 0; kk = lane; }
    else if (lane >= 16 && lane < 25) { q = 1; kk = lane - 16; }

    if (q >= 0) {
        float o1v = wi_s[warp][q][kk]      + __ldg(b_off + kk);
        float o2v = wi_s[warp][q][9 + kk]  + __ldg(b_off + 9 + kk);
        float mlg = wi_s[warp][q][18 + kk] + __ldg(b_off + 18 + kk);
        float mv  = 1.f / (1.f + __expf(-mlg));

        float pyv = o1v + (float)(yy_[q] - 1 + kk / 3);
        float pxv = o2v + (float)(xx_[q] - 1 + kk % 3);
        float yf = floorf(pyv), xf = floorf(pxv);
        float dy = pyv - yf, dx = pxv - xf;
        int iy = (int)yf, ix = (int)xf;

        int base = b_[q] << 12;
        int yc0 = min(max(iy, 0), 63),     yc1 = min(max(iy + 1, 0), 63);
        int xc0 = min(max(ix, 0), 63),     xc1 = min(max(ix + 1, 0), 63);
        float vy0 = ((unsigned)iy       < 64u) ? 1.f : 0.f;
        float vy1 = ((unsigned)(iy + 1) < 64u) ? 1.f : 0.f;
        float vx0 = ((unsigned)ix       < 64u) ? 1.f : 0.f;
        float vx1 = ((unsigned)(ix + 1) < 64u) ? 1.f : 0.f;

        int4 mi = make_int4(((base + (yc0 << 6) + xc0) << 8),
                            ((base + (yc0 << 6) + xc1) << 8),
                            ((base + (yc1 << 6) + xc0) << 8),
                            ((base + (yc1 << 6) + xc1) << 8));
        float4 mw = make_float4((1.f - dy) * (1.f - dx) * mv * vy0 * vx0,
                                (1.f - dy) * dx         * mv * vy0 * vx1,
                                dy         * (1.f - dx) * mv * vy1 * vx0,
                                dy         * dx         * mv * vy1 * vx1);
        int gp = p0 + q;
        g_midx[kk * NPIX + gp] = mi;
        g_mw[kk * NPIX + gp]   = mw;
    }
}

// ---------------------------------------------------------------------------
// Kernel 3: im2col — gather + bilinear + hi/lo split, ONCE per pixel.
// ---------------------------------------------------------------------------
__global__ __launch_bounds__(256) void im2col_kernel(const float* __restrict__ x) {
    const int tid  = threadIdx.x;
    const int pxl  = tid >> 2;
    const int cq   = tid & 3;
    const int px   = blockIdx.x * 64 + pxl;
    const int s    = blockIdx.y;           // 0..35
    const int kk   = s >> 2, cc = s & 3;

    const int4   mi = __ldg(&g_midx[kk * NPIX + px]);
    const float4 mw = __ldg(&g_mw[kk * NPIX + px]);

    uint2 ho[4], lo_[4];
#pragma unroll
    for (int j = 0; j < 4; ++j) {
        const int c = cc * 64 + cq * 16 + j * 4;
        float4 v00 = __ldg((const float4*)(x + mi.x + c));
        float4 v01 = __ldg((const float4*)(x + mi.y + c));
        float4 v10 = __ldg((const float4*)(x + mi.z + c));
        float4 v11 = __ldg((const float4*)(x + mi.w + c));
        float s0 = v00.x * mw.x + v01.x * mw.y + v10.x * mw.z + v11.x * mw.w;
        float s1 = v00.y * mw.x + v01.y * mw.y + v10.y * mw.z + v11.y * mw.w;
        float s2 = v00.z * mw.x + v01.z * mw.y + v10.z * mw.z + v11.z * mw.w;
        float s3 = v00.w * mw.x + v01.w * mw.y + v10.w * mw.z + v11.w * mw.w;

        __nv_bfloat16 h0 = __float2bfloat16(s0), h1 = __float2bfloat16(s1);
        __nv_bfloat16 h2 = __float2bfloat16(s2), h3 = __float2bfloat16(s3);
        __nv_bfloat16 l0 = __float2bfloat16(s0 - __bfloat162float(h0));
        __nv_bfloat16 l1 = __float2bfloat16(s1 - __bfloat162float(h1));
        __nv_bfloat16 l2 = __float2bfloat16(s2 - __bfloat162float(h2));
        __nv_bfloat16 l3 = __float2bfloat16(s3 - __bfloat162float(h3));

        ho[j].x  = (uint32_t)__bfloat16_as_ushort(h0) | ((uint32_t)__bfloat16_as_ushort(h1) << 16);
        ho[j].y  = (uint32_t)__bfloat16_as_ushort(h2) | ((uint32_t)__bfloat16_as_ushort(h3) << 16);
        lo_[j].x = (uint32_t)__bfloat16_as_ushort(l0) | ((uint32_t)__bfloat16_as_ushort(l1) << 16);
        lo_[j].y = (uint32_t)__bfloat16_as_ushort(l2) | ((uint32_t)__bfloat16_as_ushort(l3) << 16);
    }

    const int kstep = s * 2 + (cq >> 1);
    const int dst   = (kstep * NPIX + px) * 32 + (cq & 1) * 16;
    uint4* dh = (uint4*)(g_Ahi + dst);
    uint4* dl = (uint4*)(g_Alo + dst);
    dh[0] = make_uint4(ho[0].x, ho[0].y, ho[1].x, ho[1].y);
    dh[1] = make_uint4(ho[2].x, ho[2].y, ho[3].x, ho[3].y);
    dl[0] = make_uint4(lo_[0].x, lo_[0].y, lo_[1].x, lo_[1].y);
    dl[1] = make_uint4(lo_[2].x, lo_[2].y, lo_[3].x, lo_[3].y);
}

// ---------------------------------------------------------------------------
// Kernel 4: pure bf16 GEMM, 3-stage cp.async pipeline, SINGLE WAVE.
// CTA = 128 px x 256 f (grid 128 = 1 wave), 512 threads = 16 warps (4p x 4f),
// warp tile 32 px x 64 f. K loop: 72 k32-steps.
// D = Ahi*Bhi + Ahi*Blo + Alo*Bhi.
// ---------------------------------------------------------------------------
#define PROW    80                        // padded smem row bytes (32ch*2B + 16)
#define OFF_AHI 0
#define OFF_ALO (128 * PROW)
#define OFF_BHI (2 * 128 * PROW)
#define OFF_BLO (2 * 128 * PROW + 256 * PROW)
#define STAGE_B (2 * 128 * PROW + 2 * 256 * PROW)   // 61440 bytes
#define NSTG    3
#define SMEM_BYTES (NSTG * STAGE_B)                 // 184320

__global__ __launch_bounds__(512, 1)
void dcn_gemm_kernel(float* __restrict__ out) {
    extern __shared__ char smraw[];
    const uint32_t smb = smem_u32(smraw);

    const int tid  = threadIdx.x;
    const int wid  = tid >> 5;
    const int lane = tid & 31;
    const int p0   = blockIdx.x * 128;
    const int wp   = wid >> 2;             // warp p-block 0..3 (32 px)
    const int wf   = wid & 3;              // warp f-block 0..3 (64 f)

    const int crow = tid >> 2;             // 0..127 copy row
    const int c4   = tid & 3;              // 16B chunk within 32-ch row

    // ldmatrix lane addressing
    const int ar = lane & 15;
    const int ac = (lane >> 4) << 3;
    const int br = lane & 7;
    const int bc = ((lane >> 3) & 1) << 3;

#define COPY_STAGE(ks, st) do {                                                     \
        uint32_t _s = smb + (st) * STAGE_B;                                         \
        uint32_t _ra = crow * PROW + c4 * 16;                                       \
        const char* _ah = (const char*)(g_Ahi + ((ks) * NPIX + p0 + crow) * 32 + c4 * 8); \
        const char* _al = (const char*)(g_Alo + ((ks) * NPIX + p0 + crow) * 32 + c4 * 8); \
        CP_ASYNC16(_s + OFF_AHI + _ra, _ah);                                        \
        CP_ASYNC16(_s + OFF_ALO + _ra, _al);                                        \
        _Pragma("unroll")                                                           \
        for (int _r = 0; _r < 2; ++_r) {                                            \
            int _row = crow + _r * 128;                                             \
            uint32_t _rb = _row * PROW + c4 * 16;                                   \
            const char* _bh = (const char*)(g_wbhi + ((ks) * 256 + _row) * 32 + c4 * 8); \
            const char* _bl = (const char*)(g_wblo + ((ks) * 256 + _row) * 32 + c4 * 8); \
            CP_ASYNC16(_s + OFF_BHI + _rb, _bh);                                    \
            CP_ASYNC16(_s + OFF_BLO + _rb, _bl);                                    \
        }                                                                           \
    } while (0)

    // prologue: stages 0,1
    COPY_STAGE(0, 0); CP_COMMIT();
    COPY_STAGE(1, 1); CP_COMMIT();

    float acc[2][8][4];
#pragma unroll
    for (int m = 0; m < 2; ++m)
#pragma unroll
        for (int n = 0; n < 8; ++n)
#pragma unroll
            for (int q = 0; q < 4; ++q) acc[m][n][q] = 0.f;

    for (int ks = 0; ks < KSTEPS; ++ks) {
        CP_WAIT1();                    // stage ks landed (only ks+1 group may pend)
        __syncthreads();               // all warps done with stage (ks+2)%3 compute

        if (ks + 2 < KSTEPS) { COPY_STAGE(ks + 2, (ks + 2) % NSTG); }
        CP_COMMIT();

        const uint32_t stg = smb + (ks % NSTG) * STAGE_B;

#pragma unroll
        for (int ko = 0; ko < 2; ++ko) {
            const int k0b = ko * 32;   // 16 elems * 2B
            uint32_t ah[2][4], al[2][4];
#pragma unroll
            for (int m = 0; m < 2; ++m) {
                uint32_t aaddr = stg + OFF_AHI + (wp * 32 + m * 16 + ar) * PROW + k0b + ac * 2;
                asm volatile("ldmatrix.sync.aligned.m8n8.x4.shared.b16 {%0,%1,%2,%3}, [%4];"
                    : "=r"(ah[m][0]), "=r"(ah[m][1]), "=r"(ah[m][2]), "=r"(ah[m][3])
                    : "r"(aaddr));
                asm volatile("ldmatrix.sync.aligned.m8n8.x4.shared.b16 {%0,%1,%2,%3}, [%4];"
                    : "=r"(al[m][0]), "=r"(al[m][1]), "=r"(al[m][2]), "=r"(al[m][3])
                    : "r"(aaddr + (uint32_t)(OFF_ALO - OFF_AHI)));
            }
#pragma unroll
            for (int n = 0; n < 8; ++n) {
                uint32_t bh[2], bl[2];
                uint32_t baddr = stg + OFF_BHI + (wf * 64 + n * 8 + br) * PROW + k0b + bc * 2;
                asm volatile("ldmatrix.sync.aligned.m8n8.x2.shared.b16 {%0,%1}, [%2];"
                    : "=r"(bh[0]), "=r"(bh[1]) : "r"(baddr));
                asm volatile("ldmatrix.sync.aligned.m8n8.x2.shared.b16 {%0,%1}, [%2];"
                    : "=r"(bl[0]), "=r"(bl[1]) : "r"(baddr + (uint32_t)(OFF_BLO - OFF_BHI)));
#pragma unroll
                for (int m = 0; m < 2; ++m) {
                    float* c = acc[m][n];
#define MMA(A0,A1,A2,A3,B0,B1) \
    asm volatile("mma.sync.aligned.m16n8k16.row.col.f32.bf16.bf16.f32 " \
        "{%0,%1,%2,%3}, {%4,%5,%6,%7}, {%8,%9}, {%0,%1,%2,%3};" \
        : "+f"(c[0]), "+f"(c[1]), "+f"(c[2]), "+f"(c[3]) \
        : "r"(A0), "r"(A1), "r"(A2), "r"(A3), "r"(B0), "r"(B1))
                    MMA(ah[m][0], ah[m][1], ah[m][2], ah[m][3], bh[0], bh[1]);
                    MMA(ah[m][0], ah[m][1], ah[m][2], ah[m][3], bl[0], bl[1]);
                    MMA(al[m][0], al[m][1], al[m][2], al[m][3], bh[0], bh[1]);
#undef MMA
                }
            }
        }
    }

    // ---- epilogue: fragments -> out ----
#pragma unroll
    for (int m = 0; m < 2; ++m) {
        const int r0 = p0 + wp * 32 + m * 16 + (lane >> 2);
#pragma unroll
        for (int n = 0; n < 8; ++n) {
            const int col = wf * 64 + n * 8 + (lane & 3) * 2;
            *(float2*)(out + r0 * 256 + col)       = make_float2(acc[m][n][0], acc[m][n][1]);
            *(float2*)(out + (r0 + 8) * 256 + col) = make_float2(acc[m][n][2], acc[m][n][3]);
        }
    }
}

// ---------------------------------------------------------------------------
extern "C" void kernel_launch(void* const* d_in, const int* in_sizes, int n_in,
                              void* d_out, int out_size) {
    const float* x     = (const float*)d_in[0];   // [4,64,64,256]
    const float* w_off = (const float*)d_in[1];   // [3,3,256,27]
    const float* b_off = (const float*)d_in[2];   // [27]
    const float* filt  = (const float*)d_in[3];   // [256,256,3,3]
    float* out = (float*)d_out;                   // [4,64,64,256]

    cudaFuncSetAttribute(dcn_gemm_kernel, cudaFuncAttributeMaxDynamicSharedMemorySize, SMEM_BYTES);

    split_filt_kernel<<<2304, 256>>>(filt);
    offset_meta_kernel<<<1024, 256>>>(x, w_off, b_off);
    im2col_kernel<<<dim3(256, 36), 256>>>(x);
    dcn_gemm_kernel<<<128, 512, SMEM_BYTES>>>(out);
}

// round 7
// speedup vs baseline: 2.1645x; 1.0216x over previous
#include <cuda_runtime.h>
#include <cuda_bf16.h>
#include <cstdint>

// Problem constants
#define NPIX   16384       // B*H*W = 4*64*64
#define KSTEPS 72          // 9 taps * 8 k32-steps

// Scratch (allocation-free: __device__ globals)
__device__ int4   g_midx[9 * NPIX];          // corner element offsets (pre-multiplied by C)
__device__ float4 g_mw[9 * NPIX];            // bilinear*mask*valid weights
// B operand, split bf16 hi/lo: [kstep][f(256)][ch(32)]
__device__ __nv_bfloat16 g_wbhi[KSTEPS * 256 * 32];
__device__ __nv_bfloat16 g_wblo[KSTEPS * 256 * 32];
// Staged A (im2col output), split bf16 hi/lo: [kstep][px(16384)][ch(32)]
__device__ __nv_bfloat16 g_Ahi[KSTEPS * NPIX * 32];
__device__ __nv_bfloat16 g_Alo[KSTEPS * NPIX * 32];

__device__ __forceinline__ uint32_t smem_u32(const void* p) {
    uint32_t a;
    asm("{ .reg .u64 t; cvta.to.shared.u64 t, %1; cvt.u32.u64 %0, t; }" : "=r"(a) : "l"(p));
    return a;
}
#define CP_ASYNC16(dst_u32, src_ptr) \
    asm volatile("cp.async.cg.shared.global [%0], [%1], 16;" :: "r"(dst_u32), "l"(src_ptr))
#define CP_COMMIT()  asm volatile("cp.async.commit_group;" ::: "memory")
#define CP_WAIT1()   asm volatile("cp.async.wait_group 1;" ::: "memory")

// ---------------------------------------------------------------------------
// Kernel 1: split filt [F,C,3,3] -> bf16 hi/lo in [kstep][f][32] layout
// ---------------------------------------------------------------------------
__global__ void split_filt_kernel(const float* __restrict__ filt) {
    int i = blockIdx.x * 256 + threadIdx.x;    // 9*256*256
    int c  = i & 255;
    int f  = (i >> 8) & 255;
    int kk = i >> 16;
    float w = filt[(f * 256 + c) * 9 + kk];
    __nv_bfloat16 hi = __float2bfloat16(w);
    __nv_bfloat16 lo = __float2bfloat16(w - __bfloat162float(hi));
    int kstep = kk * 8 + (c >> 5);
    int ch    = c & 31;
    int idx   = (kstep * 256 + f) * 32 + ch;
    g_wbhi[idx] = hi;
    g_wblo[idx] = lo;
}

// ---------------------------------------------------------------------------
// Kernel 2: offset conv (3x3, C->27, SAME) + sampling metadata (proven R1)
// ---------------------------------------------------------------------------
__global__ __launch_bounds__(256) void offset_meta_kernel(
    const float* __restrict__ x, const float* __restrict__ w_off,
    const float* __restrict__ b_off) {
    __shared__ float ws[9 * 32 * 29];
    __shared__ float wi_s[8][2][27];

    const int tid  = threadIdx.x;
    const int warp = tid >> 5;
    const int lane = tid & 31;
    const int p0   = blockIdx.x * 16 + warp * 2;

    int b_[2], yy_[2], xx_[2];
#pragma unroll
    for (int q = 0; q < 2; ++q) {
        int gp = p0 + q;
        b_[q]  = gp >> 12;
        int r  = gp & 4095;
        yy_[q] = r >> 6;
        xx_[q] = r & 63;
    }

    float acc0[27], acc1[27];
#pragma unroll
    for (int o = 0; o < 27; ++o) { acc0[o] = 0.f; acc1[o] = 0.f; }

    for (int cc = 0; cc < 8; ++cc) {
        __syncthreads();
        for (int i = tid; i < 9 * 32 * 27; i += 256) {
            int tap = i / 864;
            int r   = i - tap * 864;
            int cl  = r / 27;
            int o   = r - cl * 27;
            ws[(tap * 32 + cl) * 29 + o] = w_off[(tap * 256 + cc * 32 + cl) * 27 + o];
        }
        __syncthreads();

        const int c = cc * 32 + lane;
#pragma unroll
        for (int tap = 0; tap < 9; ++tap) {
            const int ki = tap / 3, kj = tap % 3;
            float xv0, xv1;
            {
                int yy = yy_[0] - 1 + ki, xc = xx_[0] - 1 + kj;
                xv0 = ((unsigned)yy < 64u && (unsigned)xc < 64u)
                          ? __ldg(x + (((b_[0] << 12) + (yy << 6) + xc) << 8) + c) : 0.f;
            }
            {
                int yy = yy_[1] - 1 + ki, xc = xx_[1] - 1 + kj;
                xv1 = ((unsigned)yy < 64u && (unsigned)xc < 64u)
                          ? __ldg(x + (((b_[1] << 12) + (yy << 6) + xc) << 8) + c) : 0.f;
            }
            const float* wrow = &ws[(tap * 32 + lane) * 29];
#pragma unroll
            for (int o = 0; o < 27; ++o) {
                float wv = wrow[o];
                acc0[o] += wv * xv0;
                acc1[o] += wv * xv1;
            }
        }
    }

#pragma unroll
    for (int o = 0; o < 27; ++o) {
        float s0 = acc0[o], s1 = acc1[o];
#pragma unroll
        for (int sft = 16; sft; sft >>= 1) {
            s0 += __shfl_xor_sync(0xffffffffu, s0, sft);
            s1 += __shfl_xor_sync(0xffffffffu, s1, sft);
        }
        if (lane == 0) { wi_s[warp][0][o] = s0; wi_s[warp][1][o] = s1; }
    }
    __syncwarp();

    int q = -1, kk = 0;
    if (lane < 9)                     { q = 0; kk = lane; }
    else if (lane >= 16 && lane < 25) { q = 1; kk = lane - 16; }

    if (q >= 0) {
        float o1v = wi_s[warp][q][kk]      + __ldg(b_off + kk);
        float o2v = wi_s[warp][q][9 + kk]  + __ldg(b_off + 9 + kk);
        float mlg = wi_s[warp][q][18 + kk] + __ldg(b_off + 18 + kk);
        float mv  = 1.f / (1.f + __expf(-mlg));

        float pyv = o1v + (float)(yy_[q] - 1 + kk / 3);
        float pxv = o2v + (float)(xx_[q] - 1 + kk % 3);
        float yf = floorf(pyv), xf = floorf(pxv);
        float dy = pyv - yf, dx = pxv - xf;
        int iy = (int)yf, ix = (int)xf;

        int base = b_[q] << 12;
        int yc0 = min(max(iy, 0), 63),     yc1 = min(max(iy + 1, 0), 63);
        int xc0 = min(max(ix, 0), 63),     xc1 = min(max(ix + 1, 0), 63);
        float vy0 = ((unsigned)iy       < 64u) ? 1.f : 0.f;
        float vy1 = ((unsigned)(iy + 1) < 64u) ? 1.f : 0.f;
        float vx0 = ((unsigned)ix       < 64u) ? 1.f : 0.f;
        float vx1 = ((unsigned)(ix + 1) < 64u) ? 1.f : 0.f;

        int4 mi = make_int4(((base + (yc0 << 6) + xc0) << 8),
                            ((base + (yc0 << 6) + xc1) << 8),
                            ((base + (yc1 << 6) + xc0) << 8),
                            ((base + (yc1 << 6) + xc1) << 8));
        float4 mw = make_float4((1.f - dy) * (1.f - dx) * mv * vy0 * vx0,
                                (1.f - dy) * dx         * mv * vy0 * vx1,
                                dy         * (1.f - dx) * mv * vy1 * vx0,
                                dy         * dx         * mv * vy1 * vx1);
        int gp = p0 + q;
        g_midx[kk * NPIX + gp] = mi;
        g_mw[kk * NPIX + gp]   = mw;
    }
}

// ---------------------------------------------------------------------------
// Kernel 3: im2col — gather + bilinear + hi/lo split, ONCE per pixel.
// ---------------------------------------------------------------------------
__global__ __launch_bounds__(256) void im2col_kernel(const float* __restrict__ x) {
    const int tid  = threadIdx.x;
    const int pxl  = tid >> 2;
    const int cq   = tid & 3;
    const int px   = blockIdx.x * 64 + pxl;
    const int s    = blockIdx.y;           // 0..35
    const int kk   = s >> 2, cc = s & 3;

    const int4   mi = __ldg(&g_midx[kk * NPIX + px]);
    const float4 mw = __ldg(&g_mw[kk * NPIX + px]);

    uint2 ho[4], lo_[4];
#pragma unroll
    for (int j = 0; j < 4; ++j) {
        const int c = cc * 64 + cq * 16 + j * 4;
        float4 v00 = __ldg((const float4*)(x + mi.x + c));
        float4 v01 = __ldg((const float4*)(x + mi.y + c));
        float4 v10 = __ldg((const float4*)(x + mi.z + c));
        float4 v11 = __ldg((const float4*)(x + mi.w + c));
        float s0 = v00.x * mw.x + v01.x * mw.y + v10.x * mw.z + v11.x * mw.w;
        float s1 = v00.y * mw.x + v01.y * mw.y + v10.y * mw.z + v11.y * mw.w;
        float s2 = v00.z * mw.x + v01.z * mw.y + v10.z * mw.z + v11.z * mw.w;
        float s3 = v00.w * mw.x + v01.w * mw.y + v10.w * mw.z + v11.w * mw.w;

        __nv_bfloat16 h0 = __float2bfloat16(s0), h1 = __float2bfloat16(s1);
        __nv_bfloat16 h2 = __float2bfloat16(s2), h3 = __float2bfloat16(s3);
        __nv_bfloat16 l0 = __float2bfloat16(s0 - __bfloat162float(h0));
        __nv_bfloat16 l1 = __float2bfloat16(s1 - __bfloat162float(h1));
        __nv_bfloat16 l2 = __float2bfloat16(s2 - __bfloat162float(h2));
        __nv_bfloat16 l3 = __float2bfloat16(s3 - __bfloat162float(h3));

        ho[j].x  = (uint32_t)__bfloat16_as_ushort(h0) | ((uint32_t)__bfloat16_as_ushort(h1) << 16);
        ho[j].y  = (uint32_t)__bfloat16_as_ushort(h2) | ((uint32_t)__bfloat16_as_ushort(h3) << 16);
        lo_[j].x = (uint32_t)__bfloat16_as_ushort(l0) | ((uint32_t)__bfloat16_as_ushort(l1) << 16);
        lo_[j].y = (uint32_t)__bfloat16_as_ushort(l2) | ((uint32_t)__bfloat16_as_ushort(l3) << 16);
    }

    const int kstep = s * 2 + (cq >> 1);
    const int dst   = (kstep * NPIX + px) * 32 + (cq & 1) * 16;
    uint4* dh = (uint4*)(g_Ahi + dst);
    uint4* dl = (uint4*)(g_Alo + dst);
    dh[0] = make_uint4(ho[0].x, ho[0].y, ho[1].x, ho[1].y);
    dh[1] = make_uint4(ho[2].x, ho[2].y, ho[3].x, ho[3].y);
    dl[0] = make_uint4(lo_[0].x, lo_[0].y, lo_[1].x, lo_[1].y);
    dl[1] = make_uint4(lo_[2].x, lo_[2].y, lo_[3].x, lo_[3].y);
}

// ---------------------------------------------------------------------------
// Kernel 4: pure bf16 GEMM, 3-stage cp.async pipeline, SINGLE WAVE.
// CTA = 128 px x 256 f (grid 128 = 1 wave), 256 threads = 8 warps (2p x 4f),
// warp tile 64 px x 64 f (halves smem-read traffic per MMA vs 32x64).
// K loop: 72 k32-steps. D = Ahi*Bhi + Ahi*Blo + Alo*Bhi.
// ---------------------------------------------------------------------------
#define PROW    80                        // padded smem row bytes (32ch*2B + 16)
#define OFF_AHI 0
#define OFF_ALO (128 * PROW)
#define OFF_BHI (2 * 128 * PROW)
#define OFF_BLO (2 * 128 * PROW + 256 * PROW)
#define STAGE_B (2 * 128 * PROW + 2 * 256 * PROW)   // 61440 bytes
#define NSTG    3
#define SMEM_BYTES (NSTG * STAGE_B)                 // 184320

__global__ __launch_bounds__(256, 1)
void dcn_gemm_kernel(float* __restrict__ out) {
    extern __shared__ char smraw[];
    const uint32_t smb = smem_u32(smraw);

    const int tid  = threadIdx.x;
    const int wid  = tid >> 5;
    const int lane = tid & 31;
    const int p0   = blockIdx.x * 128;
    const int wp   = wid >> 2;             // warp p-block 0..1 (64 px)
    const int wf   = wid & 3;              // warp f-block 0..3 (64 f)

    const int crow = tid >> 2;             // 0..63 copy row base
    const int c4   = tid & 3;              // 16B chunk within 32-ch row

    // ldmatrix lane addressing
    const int ar = lane & 15;
    const int ac = (lane >> 4) << 3;
    const int br = lane & 7;
    const int bc = ((lane >> 3) & 1) << 3;

#define COPY_STAGE(ks, st) do {                                                     \
        uint32_t _s = smb + (st) * STAGE_B;                                         \
        _Pragma("unroll")                                                           \
        for (int _r = 0; _r < 2; ++_r) {                                            \
            int _row = crow + _r * 64;                                              \
            uint32_t _ra = _row * PROW + c4 * 16;                                   \
            const char* _ah = (const char*)(g_Ahi + ((ks) * NPIX + p0 + _row) * 32 + c4 * 8); \
            const char* _al = (const char*)(g_Alo + ((ks) * NPIX + p0 + _row) * 32 + c4 * 8); \
            CP_ASYNC16(_s + OFF_AHI + _ra, _ah);                                    \
            CP_ASYNC16(_s + OFF_ALO + _ra, _al);                                    \
        }                                                                           \
        _Pragma("unroll")                                                           \
        for (int _r = 0; _r < 4; ++_r) {                                            \
            int _row = crow + _r * 64;                                              \
            uint32_t _rb = _row * PROW + c4 * 16;                                   \
            const char* _bh = (const char*)(g_wbhi + ((ks) * 256 + _row) * 32 + c4 * 8); \
            const char* _bl = (const char*)(g_wblo + ((ks) * 256 + _row) * 32 + c4 * 8); \
            CP_ASYNC16(_s + OFF_BHI + _rb, _bh);                                    \
            CP_ASYNC16(_s + OFF_BLO + _rb, _bl);                                    \
        }                                                                           \
    } while (0)

    // prologue: stages 0,1
    COPY_STAGE(0, 0); CP_COMMIT();
    COPY_STAGE(1, 1); CP_COMMIT();

    float acc[4][8][4];
#pragma unroll
    for (int m = 0; m < 4; ++m)
#pragma unroll
        for (int n = 0; n < 8; ++n)
#pragma unroll
            for (int q = 0; q < 4; ++q) acc[m][n][q] = 0.f;

    for (int ks = 0; ks < KSTEPS; ++ks) {
        CP_WAIT1();                    // stage ks landed (only ks+1 group may pend)
        __syncthreads();               // all warps done with stage (ks+2)%3 compute

        if (ks + 2 < KSTEPS) { COPY_STAGE(ks + 2, (ks + 2) % NSTG); }
        CP_COMMIT();

        const uint32_t stg = smb + (ks % NSTG) * STAGE_B;

#pragma unroll
        for (int ko = 0; ko < 2; ++ko) {
            const int k0b = ko * 32;   // 16 elems * 2B
            uint32_t ah[4][4], al[4][4];
#pragma unroll
            for (int m = 0; m < 4; ++m) {
                uint32_t aaddr = stg + OFF_AHI + (wp * 64 + m * 16 + ar) * PROW + k0b + ac * 2;
                asm volatile("ldmatrix.sync.aligned.m8n8.x4.shared.b16 {%0,%1,%2,%3}, [%4];"
                    : "=r"(ah[m][0]), "=r"(ah[m][1]), "=r"(ah[m][2]), "=r"(ah[m][3])
                    : "r"(aaddr));
                asm volatile("ldmatrix.sync.aligned.m8n8.x4.shared.b16 {%0,%1,%2,%3}, [%4];"
                    : "=r"(al[m][0]), "=r"(al[m][1]), "=r"(al[m][2]), "=r"(al[m][3])
                    : "r"(aaddr + (uint32_t)(OFF_ALO - OFF_AHI)));
            }
#pragma unroll
            for (int n = 0; n < 8; ++n) {
                uint32_t bh[2], bl[2];
                uint32_t baddr = stg + OFF_BHI + (wf * 64 + n * 8 + br) * PROW + k0b + bc * 2;
                asm volatile("ldmatrix.sync.aligned.m8n8.x2.shared.b16 {%0,%1}, [%2];"
                    : "=r"(bh[0]), "=r"(bh[1]) : "r"(baddr));
                asm volatile("ldmatrix.sync.aligned.m8n8.x2.shared.b16 {%0,%1}, [%2];"
                    : "=r"(bl[0]), "=r"(bl[1]) : "r"(baddr + (uint32_t)(OFF_BLO - OFF_BHI)));
#pragma unroll
                for (int m = 0; m < 4; ++m) {
                    float* c = acc[m][n];
#define MMA(A0,A1,A2,A3,B0,B1) \
    asm volatile("mma.sync.aligned.m16n8k16.row.col.f32.bf16.bf16.f32 " \
        "{%0,%1,%2,%3}, {%4,%5,%6,%7}, {%8,%9}, {%0,%1,%2,%3};" \
        : "+f"(c[0]), "+f"(c[1]), "+f"(c[2]), "+f"(c[3]) \
        : "r"(A0), "r"(A1), "r"(A2), "r"(A3), "r"(B0), "r"(B1))
                    MMA(ah[m][0], ah[m][1], ah[m][2], ah[m][3], bh[0], bh[1]);
                    MMA(ah[m][0], ah[m][1], ah[m][2], ah[m][3], bl[0], bl[1]);
                    MMA(al[m][0], al[m][1], al[m][2], al[m][3], bh[0], bh[1]);
#undef MMA
                }
            }
        }
    }

    // ---- epilogue: fragments -> out ----
#pragma unroll
    for (int m = 0; m < 4; ++m) {
        const int r0 = p0 + wp * 64 + m * 16 + (lane >> 2);
#pragma unroll
        for (int n = 0; n < 8; ++n) {
            const int col = wf * 64 + n * 8 + (lane & 3) * 2;
            *(float2*)(out + r0 * 256 + col)       = make_float2(acc[m][n][0], acc[m][n][1]);
            *(float2*)(out + (r0 + 8) * 256 + col) = make_float2(acc[m][n][2], acc[m][n][3]);
        }
    }
}

// ---------------------------------------------------------------------------
extern "C" void kernel_launch(void* const* d_in, const int* in_sizes, int n_in,
                              void* d_out, int out_size) {
    const float* x     = (const float*)d_in[0];   // [4,64,64,256]
    const float* w_off = (const float*)d_in[1];   // [3,3,256,27]
    const float* b_off = (const float*)d_in[2];   // [27]
    const float* filt  = (const float*)d_in[3];   // [256,256,3,3]
    float* out = (float*)d_out;                   // [4,64,64,256]

    cudaFuncSetAttribute(dcn_gemm_kernel, cudaFuncAttributeMaxDynamicSharedMemorySize, SMEM_BYTES);

    split_filt_kernel<<<2304, 256>>>(filt);
    offset_meta_kernel<<<1024, 256>>>(x, w_off, b_off);
    im2col_kernel<<<dim3(256, 36), 256>>>(x);
    dcn_gemm_kernel<<<128, 256, SMEM_BYTES>>>(out);
}

// round 8
// speedup vs baseline: 2.3504x; 1.0859x over previous
#include <cuda_runtime.h>
#include <cuda_bf16.h>
#include <cstdint>

// Problem constants
#define NPIX   16384       // B*H*W = 4*64*64
#define KSTEPS 72          // 9 taps * 8 k32-steps

// Scratch (allocation-free: __device__ globals)
__device__ int4   g_midx[9 * NPIX];          // corner element offsets (pre-multiplied by C)
__device__ float4 g_mw[9 * NPIX];            // bilinear*mask*valid weights
// B operand, split bf16 hi/lo: [kstep][f(256)][ch(32)]
__device__ __nv_bfloat16 g_wbhi[KSTEPS * 256 * 32];
__device__ __nv_bfloat16 g_wblo[KSTEPS * 256 * 32];
// Staged A (im2col output), split bf16 hi/lo: [kstep][px(16384)][ch(32)]
__device__ __nv_bfloat16 g_Ahi[KSTEPS * NPIX * 32];
__device__ __nv_bfloat16 g_Alo[KSTEPS * NPIX * 32];

__device__ __forceinline__ uint32_t smem_u32(const void* p) {
    uint32_t a;
    asm("{ .reg .u64 t; cvta.to.shared.u64 t, %1; cvt.u32.u64 %0, t; }" : "=r"(a) : "l"(p));
    return a;
}
#define CP_ASYNC16(dst_u32, src_ptr) \
    asm volatile("cp.async.cg.shared.global [%0], [%1], 16;" :: "r"(dst_u32), "l"(src_ptr))
#define CP_COMMIT()  asm volatile("cp.async.commit_group;" ::: "memory")
#define CP_WAIT2()   asm volatile("cp.async.wait_group 2;" ::: "memory")

// ---------------------------------------------------------------------------
// Kernel 1: split filt [F,C,3,3] -> bf16 hi/lo in [kstep][f][32] layout
// ---------------------------------------------------------------------------
__global__ void split_filt_kernel(const float* __restrict__ filt) {
    int i = blockIdx.x * 256 + threadIdx.x;    // 9*256*256
    int c  = i & 255;
    int f  = (i >> 8) & 255;
    int kk = i >> 16;
    float w = filt[(f * 256 + c) * 9 + kk];
    __nv_bfloat16 hi = __float2bfloat16(w);
    __nv_bfloat16 lo = __float2bfloat16(w - __bfloat162float(hi));
    int kstep = kk * 8 + (c >> 5);
    int ch    = c & 31;
    int idx   = (kstep * 256 + f) * 32 + ch;
    g_wbhi[idx] = hi;
    g_wblo[idx] = lo;
}

// ---------------------------------------------------------------------------
// Kernel 2: offset conv (3x3, C->27, SAME) + metadata. 4 pixels per warp
// (halves smem weight-read traffic per pixel vs 2-px version).
// ---------------------------------------------------------------------------
__global__ __launch_bounds__(256) void offset_meta_kernel(
    const float* __restrict__ x, const float* __restrict__ w_off,
    const float* __restrict__ b_off) {
    __shared__ float ws[9 * 32 * 29];
    __shared__ float wi_s[8][4][27];

    const int tid  = threadIdx.x;
    const int warp = tid >> 5;
    const int lane = tid & 31;
    const int p0   = blockIdx.x * 32 + warp * 4;

    int b_[4], yy_[4], xx_[4];
#pragma unroll
    for (int q = 0; q < 4; ++q) {
        int gp = p0 + q;
        b_[q]  = gp >> 12;
        int r  = gp & 4095;
        yy_[q] = r >> 6;
        xx_[q] = r & 63;
    }

    float acc[4][27];
#pragma unroll
    for (int q = 0; q < 4; ++q)
#pragma unroll
        for (int o = 0; o < 27; ++o) acc[q][o] = 0.f;

    for (int cc = 0; cc < 8; ++cc) {
        __syncthreads();
        for (int i = tid; i < 9 * 32 * 27; i += 256) {
            int tap = i / 864;
            int r   = i - tap * 864;
            int cl  = r / 27;
            int o   = r - cl * 27;
            ws[(tap * 32 + cl) * 29 + o] = w_off[(tap * 256 + cc * 32 + cl) * 27 + o];
        }
        __syncthreads();

        const int c = cc * 32 + lane;
#pragma unroll
        for (int tap = 0; tap < 9; ++tap) {
            const int ki = tap / 3, kj = tap % 3;
            float xv[4];
#pragma unroll
            for (int q = 0; q < 4; ++q) {
                int yy = yy_[q] - 1 + ki, xc = xx_[q] - 1 + kj;
                xv[q] = ((unsigned)yy < 64u && (unsigned)xc < 64u)
                          ? __ldg(x + (((b_[q] << 12) + (yy << 6) + xc) << 8) + c) : 0.f;
            }
            const float* wrow = &ws[(tap * 32 + lane) * 29];
#pragma unroll
            for (int o = 0; o < 27; ++o) {
                float wv = wrow[o];
#pragma unroll
                for (int q = 0; q < 4; ++q) acc[q][o] += wv * xv[q];
            }
        }
    }

#pragma unroll
    for (int o = 0; o < 27; ++o) {
        float s0 = acc[0][o], s1 = acc[1][o], s2 = acc[2][o], s3 = acc[3][o];
#pragma unroll
        for (int sft = 16; sft; sft >>= 1) {
            s0 += __shfl_xor_sync(0xffffffffu, s0, sft);
            s1 += __shfl_xor_sync(0xffffffffu, s1, sft);
            s2 += __shfl_xor_sync(0xffffffffu, s2, sft);
            s3 += __shfl_xor_sync(0xffffffffu, s3, sft);
        }
        if (lane == 0) {
            wi_s[warp][0][o] = s0; wi_s[warp][1][o] = s1;
            wi_s[warp][2][o] = s2; wi_s[warp][3][o] = s3;
        }
    }
    __syncwarp();

#pragma unroll
    for (int pass = 0; pass < 2; ++pass) {
        int q = -1, kk = 0;
        if (lane < 9)                     { q = pass * 2;     kk = lane; }
        else if (lane >= 16 && lane < 25) { q = pass * 2 + 1; kk = lane - 16; }

        if (q >= 0) {
            float o1v = wi_s[warp][q][kk]      + __ldg(b_off + kk);
            float o2v = wi_s[warp][q][9 + kk]  + __ldg(b_off + 9 + kk);
            float mlg = wi_s[warp][q][18 + kk] + __ldg(b_off + 18 + kk);
            float mv  = 1.f / (1.f + __expf(-mlg));

            float pyv = o1v + (float)(yy_[q] - 1 + kk / 3);
            float pxv = o2v + (float)(xx_[q] - 1 + kk % 3);
            float yf = floorf(pyv), xf = floorf(pxv);
            float dy = pyv - yf, dx = pxv - xf;
            int iy = (int)yf, ix = (int)xf;

            int base = b_[q] << 12;
            int yc0 = min(max(iy, 0), 63),     yc1 = min(max(iy + 1, 0), 63);
            int xc0 = min(max(ix, 0), 63),     xc1 = min(max(ix + 1, 0), 63);
            float vy0 = ((unsigned)iy       < 64u) ? 1.f : 0.f;
            float vy1 = ((unsigned)(iy + 1) < 64u) ? 1.f : 0.f;
            float vx0 = ((unsigned)ix       < 64u) ? 1.f : 0.f;
            float vx1 = ((unsigned)(ix + 1) < 64u) ? 1.f : 0.f;

            int4 mi = make_int4(((base + (yc0 << 6) + xc0) << 8),
                                ((base + (yc0 << 6) + xc1) << 8),
                                ((base + (yc1 << 6) + xc0) << 8),
                                ((base + (yc1 << 6) + xc1) << 8));
            float4 mw = make_float4((1.f - dy) * (1.f - dx) * mv * vy0 * vx0,
                                    (1.f - dy) * dx         * mv * vy0 * vx1,
                                    dy         * (1.f - dx) * mv * vy1 * vx0,
                                    dy         * dx         * mv * vy1 * vx1);
            int gp = p0 + q;
            g_midx[kk * NPIX + gp] = mi;
            g_mw[kk * NPIX + gp]   = mw;
        }
    }
}

// ---------------------------------------------------------------------------
// Kernel 3: im2col — gather + bilinear + hi/lo split, ONCE per pixel.
// ---------------------------------------------------------------------------
__global__ __launch_bounds__(256) void im2col_kernel(const float* __restrict__ x) {
    const int tid  = threadIdx.x;
    const int pxl  = tid >> 2;
    const int cq   = tid & 3;
    const int px   = blockIdx.x * 64 + pxl;
    const int s    = blockIdx.y;           // 0..35
    const int kk   = s >> 2, cc = s & 3;

    const int4   mi = __ldg(&g_midx[kk * NPIX + px]);
    const float4 mw = __ldg(&g_mw[kk * NPIX + px]);

    uint2 ho[4], lo_[4];
#pragma unroll
    for (int j = 0; j < 4; ++j) {
        const int c = cc * 64 + cq * 16 + j * 4;
        float4 v00 = __ldg((const float4*)(x + mi.x + c));
        float4 v01 = __ldg((const float4*)(x + mi.y + c));
        float4 v10 = __ldg((const float4*)(x + mi.z + c));
        float4 v11 = __ldg((const float4*)(x + mi.w + c));
        float s0 = v00.x * mw.x + v01.x * mw.y + v10.x * mw.z + v11.x * mw.w;
        float s1 = v00.y * mw.x + v01.y * mw.y + v10.y * mw.z + v11.y * mw.w;
        float s2 = v00.z * mw.x + v01.z * mw.y + v10.z * mw.z + v11.z * mw.w;
        float s3 = v00.w * mw.x + v01.w * mw.y + v10.w * mw.z + v11.w * mw.w;

        __nv_bfloat16 h0 = __float2bfloat16(s0), h1 = __float2bfloat16(s1);
        __nv_bfloat16 h2 = __float2bfloat16(s2), h3 = __float2bfloat16(s3);
        __nv_bfloat16 l0 = __float2bfloat16(s0 - __bfloat162float(h0));
        __nv_bfloat16 l1 = __float2bfloat16(s1 - __bfloat162float(h1));
        __nv_bfloat16 l2 = __float2bfloat16(s2 - __bfloat162float(h2));
        __nv_bfloat16 l3 = __float2bfloat16(s3 - __bfloat162float(h3));

        ho[j].x  = (uint32_t)__bfloat16_as_ushort(h0) | ((uint32_t)__bfloat16_as_ushort(h1) << 16);
        ho[j].y  = (uint32_t)__bfloat16_as_ushort(h2) | ((uint32_t)__bfloat16_as_ushort(h3) << 16);
        lo_[j].x = (uint32_t)__bfloat16_as_ushort(l0) | ((uint32_t)__bfloat16_as_ushort(l1) << 16);
        lo_[j].y = (uint32_t)__bfloat16_as_ushort(l2) | ((uint32_t)__bfloat16_as_ushort(l3) << 16);
    }

    const int kstep = s * 2 + (cq >> 1);
    const int dst   = (kstep * NPIX + px) * 32 + (cq & 1) * 16;
    uint4* dh = (uint4*)(g_Ahi + dst);
    uint4* dl = (uint4*)(g_Alo + dst);
    dh[0] = make_uint4(ho[0].x, ho[0].y, ho[1].x, ho[1].y);
    dh[1] = make_uint4(ho[2].x, ho[2].y, ho[3].x, ho[3].y);
    dl[0] = make_uint4(lo_[0].x, lo_[0].y, lo_[1].x, lo_[1].y);
    dl[1] = make_uint4(lo_[2].x, lo_[2].y, lo_[3].x, lo_[3].y);
}

// ---------------------------------------------------------------------------
// Kernel 4: pure bf16 GEMM, 4-stage cp.async pipeline, XOR-swizzled smem,
// dependency-broken 3-pass MMA schedule. CTA = 128 px x 256 f (grid 128 =
// 1 wave), 256 threads = 8 warps (2p x 4f), warp tile 64x64.
// Smem rows: 64B (4 x 16B chunks), chunk' = chunk ^ ((row>>1)&3).
// ---------------------------------------------------------------------------
#define OFF_ALO 8192
#define OFF_BHI 16384
#define OFF_BLO 32768
#define STAGE_B 49152
#define NSTG    4
#define SMEM_BYTES (NSTG * STAGE_B)      // 196608

__global__ __launch_bounds__(256, 1)
void dcn_gemm_kernel(float* __restrict__ out) {
    extern __shared__ char smraw[];
    const uint32_t smb = smem_u32(smraw);

    const int tid  = threadIdx.x;
    const int wid  = tid >> 5;
    const int lane = tid & 31;
    const int p0   = blockIdx.x * 128;
    const int wp   = wid >> 2;             // warp p-block 0..1 (64 px)
    const int wf   = wid & 3;              // warp f-block 0..3 (64 f)

    // ldmatrix lane addressing
    const int ar  = lane & 15;             // A row within 16
    const int a16 = lane >> 4;             // A 16B-chunk half (0/1)
    const int br  = lane & 7;              // B row within 8
    const int b1  = (lane >> 3) & 1;       // B 16B-chunk half (0/1)

#define COPY_STAGE(ks, st) do {                                                     \
        uint32_t _s = smb + (st) * STAGE_B;                                         \
        _Pragma("unroll")                                                           \
        for (int _i = 0; _i < 2; ++_i) {                                            \
            int _idx = tid + _i * 256;          /* 0..511 */                        \
            int _row = _idx >> 2, _ch = _idx & 3;                                   \
            uint32_t _d = _s + _row * 64 + ((_ch ^ ((_row >> 1) & 3)) << 4);        \
            const char* _ah = (const char*)(g_Ahi + ((ks) * NPIX + p0 + _row) * 32 + _ch * 8); \
            const char* _al = (const char*)(g_Alo + ((ks) * NPIX + p0 + _row) * 32 + _ch * 8); \
            CP_ASYNC16(_d, _ah);                                                    \
            CP_ASYNC16(_d + OFF_ALO, _al);                                          \
        }                                                                           \
        _Pragma("unroll")                                                           \
        for (int _i = 0; _i < 4; ++_i) {                                            \
            int _idx = tid + _i * 256;          /* 0..1023 */                       \
            int _row = _idx >> 2, _ch = _idx & 3;                                   \
            uint32_t _d = _s + OFF_BHI + _row * 64 + ((_ch ^ ((_row >> 1) & 3)) << 4); \
            const char* _bh = (const char*)(g_wbhi + ((ks) * 256 + _row) * 32 + _ch * 8); \
            const char* _bl = (const char*)(g_wblo + ((ks) * 256 + _row) * 32 + _ch * 8); \
            CP_ASYNC16(_d, _bh);                                                    \
            CP_ASYNC16(_d + (OFF_BLO - OFF_BHI), _bl);                              \
        }                                                                           \
    } while (0)

    // prologue: stages 0,1,2
    COPY_STAGE(0, 0); CP_COMMIT();
    COPY_STAGE(1, 1); CP_COMMIT();
    COPY_STAGE(2, 2); CP_COMMIT();

    float acc[4][8][4];
#pragma unroll
    for (int m = 0; m < 4; ++m)
#pragma unroll
        for (int n = 0; n < 8; ++n)
#pragma unroll
            for (int q = 0; q < 4; ++q) acc[m][n][q] = 0.f;

    for (int ks = 0; ks < KSTEPS; ++ks) {
        CP_WAIT2();                    // stage ks landed (2 younger groups pend)
        __syncthreads();               // visible to all; stage (ks+3)%4 free

        if (ks + 3 < KSTEPS) { COPY_STAGE(ks + 3, (ks + 3) & 3); }
        CP_COMMIT();                   // unconditional: keeps group count exact

        const uint32_t stg = smb + (ks & 3) * STAGE_B;

#pragma unroll
        for (int ko = 0; ko < 2; ++ko) {
            // ---- load ALL fragments first (independence for scheduler) ----
            uint32_t ah[4][4], al[4][4];
#pragma unroll
            for (int m = 0; m < 4; ++m) {
                int row = wp * 64 + m * 16 + ar;
                uint32_t aaddr = stg + row * 64 +
                    (uint32_t)((((ko * 2 + a16) ^ ((row >> 1) & 3)) << 4));
                asm volatile("ldmatrix.sync.aligned.m8n8.x4.shared.b16 {%0,%1,%2,%3}, [%4];"
                    : "=r"(ah[m][0]), "=r"(ah[m][1]), "=r"(ah[m][2]), "=r"(ah[m][3])
                    : "r"(aaddr));
                asm volatile("ldmatrix.sync.aligned.m8n8.x4.shared.b16 {%0,%1,%2,%3}, [%4];"
                    : "=r"(al[m][0]), "=r"(al[m][1]), "=r"(al[m][2]), "=r"(al[m][3])
                    : "r"(aaddr + (uint32_t)OFF_ALO));
            }
            uint32_t bh[8][2], bl[8][2];
#pragma unroll
            for (int n = 0; n < 8; ++n) {
                int row = wf * 64 + n * 8 + br;
                uint32_t baddr = stg + OFF_BHI + row * 64 +
                    (uint32_t)((((ko * 2 + b1) ^ ((row >> 1) & 3)) << 4));
                asm volatile("ldmatrix.sync.aligned.m8n8.x2.shared.b16 {%0,%1}, [%2];"
                    : "=r"(bh[n][0]), "=r"(bh[n][1]) : "r"(baddr));
                asm volatile("ldmatrix.sync.aligned.m8n8.x2.shared.b16 {%0,%1}, [%2];"
                    : "=r"(bl[n][0]), "=r"(bl[n][1]) : "r"(baddr + (uint32_t)(OFF_BLO - OFF_BHI)));
            }

#define MMA(c, A0,A1,A2,A3,B0,B1) \
    asm volatile("mma.sync.aligned.m16n8k16.row.col.f32.bf16.bf16.f32 " \
        "{%0,%1,%2,%3}, {%4,%5,%6,%7}, {%8,%9}, {%0,%1,%2,%3};" \
        : "+f"((c)[0]), "+f"((c)[1]), "+f"((c)[2]), "+f"((c)[3]) \
        : "r"(A0), "r"(A1), "r"(A2), "r"(A3), "r"(B0), "r"(B1))

            // ---- pass 1: Ahi*Bhi (32 independent MMAs) ----
#pragma unroll
            for (int m = 0; m < 4; ++m)
#pragma unroll
                for (int n = 0; n < 8; ++n)
                    MMA(acc[m][n], ah[m][0], ah[m][1], ah[m][2], ah[m][3], bh[n][0], bh[n][1]);
            // ---- pass 2: Alo*Bhi (acc reuse at distance 32) ----
#pragma unroll
            for (int m = 0; m < 4; ++m)
#pragma unroll
                for (int n = 0; n < 8; ++n)
                    MMA(acc[m][n], al[m][0], al[m][1], al[m][2], al[m][3], bh[n][0], bh[n][1]);
            // ---- pass 3: Ahi*Blo ----
#pragma unroll
            for (int m = 0; m < 4; ++m)
#pragma unroll
                for (int n = 0; n < 8; ++n)
                    MMA(acc[m][n], ah[m][0], ah[m][1], ah[m][2], ah[m][3], bl[n][0], bl[n][1]);
#undef MMA
        }
    }

    // ---- epilogue: fragments -> out ----
#pragma unroll
    for (int m = 0; m < 4; ++m) {
        const int r0 = p0 + wp * 64 + m * 16 + (lane >> 2);
#pragma unroll
        for (int n = 0; n < 8; ++n) {
            const int col = wf * 64 + n * 8 + (lane & 3) * 2;
            *(float2*)(out + r0 * 256 + col)       = make_float2(acc[m][n][0], acc[m][n][1]);
            *(float2*)(out + (r0 + 8) * 256 + col) = make_float2(acc[m][n][2], acc[m][n][3]);
        }
    }
}

// ---------------------------------------------------------------------------
extern "C" void kernel_launch(void* const* d_in, const int* in_sizes, int n_in,
                              void* d_out, int out_size) {
    const float* x     = (const float*)d_in[0];   // [4,64,64,256]
    const float* w_off = (const float*)d_in[1];   // [3,3,256,27]
    const float* b_off = (const float*)d_in[2];   // [27]
    const float* filt  = (const float*)d_in[3];   // [256,256,3,3]
    float* out = (float*)d_out;                   // [4,64,64,256]

    cudaFuncSetAttribute(dcn_gemm_kernel, cudaFuncAttributeMaxDynamicSharedMemorySize, SMEM_BYTES);

    split_filt_kernel<<<2304, 256>>>(filt);
    offset_meta_kernel<<<512, 256>>>(x, w_off, b_off);
    im2col_kernel<<<dim3(256, 36), 256>>>(x);
    dcn_gemm_kernel<<<128, 256, SMEM_BYTES>>>(out);
}

// round 9
// speedup vs baseline: 2.7215x; 1.1579x over previous
#include <cuda_runtime.h>
#include <cuda_bf16.h>
#include <cstdint>

// Problem constants
#define NPIX   16384       // B*H*W = 4*64*64
#define KSTEPS 72          // 9 taps * 8 k32-steps

// Scratch (allocation-free: __device__ globals)
__device__ int4   g_midx[9 * NPIX];          // corner element offsets (pre-multiplied by C)
__device__ float4 g_mw[9 * NPIX];            // bilinear*mask*valid weights
// B operand, split bf16 hi/lo: [kstep][f(256)][ch(32)]
__device__ __nv_bfloat16 g_wbhi[KSTEPS * 256 * 32];
__device__ __nv_bfloat16 g_wblo[KSTEPS * 256 * 32];

__device__ __forceinline__ uint32_t smem_u32(const void* p) {
    uint32_t a;
    asm("{ .reg .u64 t; cvta.to.shared.u64 t, %1; cvt.u32.u64 %0, t; }" : "=r"(a) : "l"(p));
    return a;
}
#define CP_ASYNC16(dst_u32, src_ptr) \
    asm volatile("cp.async.cg.shared.global [%0], [%1], 16;" :: "r"(dst_u32), "l"(src_ptr))
#define CP_COMMIT()  asm volatile("cp.async.commit_group;" ::: "memory")
#define CP_WAIT1()   asm volatile("cp.async.wait_group 1;" ::: "memory")

// ---------------------------------------------------------------------------
// Kernel 1: split filt [F,C,3,3] -> bf16 hi/lo in [kstep][f][32] layout
// ---------------------------------------------------------------------------
__global__ void split_filt_kernel(const float* __restrict__ filt) {
    int i = blockIdx.x * 256 + threadIdx.x;    // 9*256*256
    int c  = i & 255;
    int f  = (i >> 8) & 255;
    int kk = i >> 16;
    float w = filt[(f * 256 + c) * 9 + kk];
    __nv_bfloat16 hi = __float2bfloat16(w);
    __nv_bfloat16 lo = __float2bfloat16(w - __bfloat162float(hi));
    int kstep = kk * 8 + (c >> 5);
    int ch    = c & 31;
    int idx   = (kstep * 256 + f) * 32 + ch;
    g_wbhi[idx] = hi;
    g_wblo[idx] = lo;
}

// ---------------------------------------------------------------------------
// Kernel 2: offset conv (3x3, C->27, SAME) + metadata. 4 pixels per warp.
// ---------------------------------------------------------------------------
__global__ __launch_bounds__(256) void offset_meta_kernel(
    const float* __restrict__ x, const float* __restrict__ w_off,
    const float* __restrict__ b_off) {
    __shared__ float ws[9 * 32 * 29];
    __shared__ float wi_s[8][4][27];

    const int tid  = threadIdx.x;
    const int warp = tid >> 5;
    const int lane = tid & 31;
    const int p0   = blockIdx.x * 32 + warp * 4;

    int b_[4], yy_[4], xx_[4];
#pragma unroll
    for (int q = 0; q < 4; ++q) {
        int gp = p0 + q;
        b_[q]  = gp >> 12;
        int r  = gp & 4095;
        yy_[q] = r >> 6;
        xx_[q] = r & 63;
    }

    float acc[4][27];
#pragma unroll
    for (int q = 0; q < 4; ++q)
#pragma unroll
        for (int o = 0; o < 27; ++o) acc[q][o] = 0.f;

    for (int cc = 0; cc < 8; ++cc) {
        __syncthreads();
        for (int i = tid; i < 9 * 32 * 27; i += 256) {
            int tap = i / 864;
            int r   = i - tap * 864;
            int cl  = r / 27;
            int o   = r - cl * 27;
            ws[(tap * 32 + cl) * 29 + o] = w_off[(tap * 256 + cc * 32 + cl) * 27 + o];
        }
        __syncthreads();

        const int c = cc * 32 + lane;
#pragma unroll
        for (int tap = 0; tap < 9; ++tap) {
            const int ki = tap / 3, kj = tap % 3;
            float xv[4];
#pragma unroll
            for (int q = 0; q < 4; ++q) {
                int yy = yy_[q] - 1 + ki, xc = xx_[q] - 1 + kj;
                xv[q] = ((unsigned)yy < 64u && (unsigned)xc < 64u)
                          ? __ldg(x + (((b_[q] << 12) + (yy << 6) + xc) << 8) + c) : 0.f;
            }
            const float* wrow = &ws[(tap * 32 + lane) * 29];
#pragma unroll
            for (int o = 0; o < 27; ++o) {
                float wv = wrow[o];
#pragma unroll
                for (int q = 0; q < 4; ++q) acc[q][o] += wv * xv[q];
            }
        }
    }

#pragma unroll
    for (int o = 0; o < 27; ++o) {
        float s0 = acc[0][o], s1 = acc[1][o], s2 = acc[2][o], s3 = acc[3][o];
#pragma unroll
        for (int sft = 16; sft; sft >>= 1) {
            s0 += __shfl_xor_sync(0xffffffffu, s0, sft);
            s1 += __shfl_xor_sync(0xffffffffu, s1, sft);
            s2 += __shfl_xor_sync(0xffffffffu, s2, sft);
            s3 += __shfl_xor_sync(0xffffffffu, s3, sft);
        }
        if (lane == 0) {
            wi_s[warp][0][o] = s0; wi_s[warp][1][o] = s1;
            wi_s[warp][2][o] = s2; wi_s[warp][3][o] = s3;
        }
    }
    __syncwarp();

#pragma unroll
    for (int pass = 0; pass < 2; ++pass) {
        int q = -1, kk = 0;
        if (lane < 9)                     { q = pass * 2;     kk = lane; }
        else if (lane >= 16 && lane < 25) { q = pass * 2 + 1; kk = lane - 16; }

        if (q >= 0) {
            float o1v = wi_s[warp][q][kk]      + __ldg(b_off + kk);
            float o2v = wi_s[warp][q][9 + kk]  + __ldg(b_off + 9 + kk);
            float mlg = wi_s[warp][q][18 + kk] + __ldg(b_off + 18 + kk);
            float mv  = 1.f / (1.f + __expf(-mlg));

            float pyv = o1v + (float)(yy_[q] - 1 + kk / 3);
            float pxv = o2v + (float)(xx_[q] - 1 + kk % 3);
            float yf = floorf(pyv), xf = floorf(pxv);
            float dy = pyv - yf, dx = pxv - xf;
            int iy = (int)yf, ix = (int)xf;

            int base = b_[q] << 12;
            int yc0 = min(max(iy, 0), 63),     yc1 = min(max(iy + 1, 0), 63);
            int xc0 = min(max(ix, 0), 63),     xc1 = min(max(ix + 1, 0), 63);
            float vy0 = ((unsigned)iy       < 64u) ? 1.f : 0.f;
            float vy1 = ((unsigned)(iy + 1) < 64u) ? 1.f : 0.f;
            float vx0 = ((unsigned)ix       < 64u) ? 1.f : 0.f;
            float vx1 = ((unsigned)(ix + 1) < 64u) ? 1.f : 0.f;

            int4 mi = make_int4(((base + (yc0 << 6) + xc0) << 8),
                                ((base + (yc0 << 6) + xc1) << 8),
                                ((base + (yc1 << 6) + xc0) << 8),
                                ((base + (yc1 << 6) + xc1) << 8));
            float4 mw = make_float4((1.f - dy) * (1.f - dx) * mv * vy0 * vx0,
                                    (1.f - dy) * dx         * mv * vy0 * vx1,
                                    dy         * (1.f - dx) * mv * vy1 * vx0,
                                    dy         * dx         * mv * vy1 * vx1);
            int gp = p0 + q;
            g_midx[kk * NPIX + gp] = mi;
            g_mw[kk * NPIX + gp]   = mw;
        }
    }
}

// ---------------------------------------------------------------------------
// Kernel 3: FUSED gather + bf16 GEMM. CTA = 128 px x 256 f, grid 128 = 1 wave,
// 256 threads = 8 warps (2p x 4f), warp tile 64x64, 3-pass split-precision.
// A built in smem by in-kernel gather (no HBM staging); B via cp.async, 3-stage.
// Smem stage: A 128x32ch hi/lo (16KB) + B 256x32ch hi/lo (32KB) = 48KB.
// Row = 64B (4 x 16B chunks), chunk' = chunk ^ ((row>>1)&3).
// ---------------------------------------------------------------------------
#define OFF_ALO 8192
#define OFF_BHI 16384
#define OFF_BLO 32768
#define STAGE_B 49152
#define NSTG    3
#define META_OFF (NSTG * STAGE_B)                    // 147456
#define SMEM_BYTES (META_OFF + 1152 * 16 * 2)        // +36KB meta = 184320

__global__ __launch_bounds__(256, 1)
void dcn_gemm_kernel(const float* __restrict__ x, float* __restrict__ out) {
    extern __shared__ char smraw[];
    char* smp = smraw;
    const uint32_t smb = smem_u32(smraw);

    int4*   mi_s = (int4*)(smp + META_OFF);
    float4* mw_s = (float4*)(mi_s + 1152);

    const int tid  = threadIdx.x;
    const int wid  = tid >> 5;
    const int lane = tid & 31;
    const int p0   = blockIdx.x * 128;
    const int wp   = wid >> 2;             // warp p-block 0..1 (64 px)
    const int wf   = wid & 3;              // warp f-block 0..3 (64 f)

    const int gpx = tid >> 2;              // gather pixel-local (0..63) per half
    const int gcq = tid & 3;               // gather 8-ch chunk id (0..3)

    // ldmatrix lane addressing
    const int ar  = lane & 15;
    const int a16 = lane >> 4;
    const int br  = lane & 7;
    const int b1  = (lane >> 3) & 1;

    // ---- preload metadata: 9 taps x 128 px ----
    for (int i = tid; i < 1152; i += 256) {
        int kk = i >> 7, pp = i & 127;
        mi_s[i] = g_midx[kk * NPIX + p0 + pp];
        mw_s[i] = g_mw[kk * NPIX + p0 + pp];
    }

#define COPY_B(ks, st) do {                                                         \
        uint32_t _s = smb + (st) * STAGE_B + OFF_BHI;                               \
        _Pragma("unroll")                                                           \
        for (int _i = 0; _i < 4; ++_i) {                                            \
            int _idx = tid + _i * 256;                                              \
            int _row = _idx >> 2, _ch = _idx & 3;                                   \
            uint32_t _d = _s + _row * 64 + ((_ch ^ ((_row >> 1) & 3)) << 4);        \
            const char* _bh = (const char*)(g_wbhi + ((ks) * 256 + _row) * 32 + _ch * 8); \
            const char* _bl = (const char*)(g_wblo + ((ks) * 256 + _row) * 32 + _ch * 8); \
            CP_ASYNC16(_d, _bh);                                                    \
            CP_ASYNC16(_d + (OFF_BLO - OFF_BHI), _bl);                              \
        }                                                                           \
    } while (0)

// gather loads for kstep ksn, half po -> V[8] (float4)
#define GATHER_LDG(ksn, po, V) do {                                                 \
        const int _kk = (ksn) >> 3;                                                 \
        const int _cb = ((ksn) & 7) * 32;                                           \
        const int _px = (po) * 64 + gpx;                                            \
        const int4 _mi = mi_s[_kk * 128 + _px];                                     \
        _Pragma("unroll")                                                           \
        for (int _j = 0; _j < 2; ++_j) {                                            \
            const int _c = _cb + gcq * 8 + _j * 4;                                  \
            V[_j * 4 + 0] = __ldg((const float4*)(x + _mi.x + _c));                 \
            V[_j * 4 + 1] = __ldg((const float4*)(x + _mi.y + _c));                 \
            V[_j * 4 + 2] = __ldg((const float4*)(x + _mi.z + _c));                 \
            V[_j * 4 + 3] = __ldg((const float4*)(x + _mi.w + _c));                 \
        }                                                                           \
    } while (0)

// convert V -> bf16 hi/lo, store one 16B chunk each to stage st
#define GATHER_STS(ksn, st, po, V) do {                                             \
        const int _kk = (ksn) >> 3;                                                 \
        const int _px = (po) * 64 + gpx;                                            \
        const float4 _w = mw_s[_kk * 128 + _px];                                    \
        uint32_t _h[4], _l[4];                                                      \
        _Pragma("unroll")                                                           \
        for (int _j = 0; _j < 2; ++_j) {                                            \
            float4 _v00 = V[_j * 4 + 0], _v01 = V[_j * 4 + 1];                      \
            float4 _v10 = V[_j * 4 + 2], _v11 = V[_j * 4 + 3];                      \
            float _s0 = _v00.x * _w.x + _v01.x * _w.y + _v10.x * _w.z + _v11.x * _w.w; \
            float _s1 = _v00.y * _w.x + _v01.y * _w.y + _v10.y * _w.z + _v11.y * _w.w; \
            float _s2 = _v00.z * _w.x + _v01.z * _w.y + _v10.z * _w.z + _v11.z * _w.w; \
            float _s3 = _v00.w * _w.x + _v01.w * _w.y + _v10.w * _w.z + _v11.w * _w.w; \
            __nv_bfloat16 _h0 = __float2bfloat16(_s0), _h1 = __float2bfloat16(_s1); \
            __nv_bfloat16 _h2 = __float2bfloat16(_s2), _h3 = __float2bfloat16(_s3); \
            __nv_bfloat16 _l0 = __float2bfloat16(_s0 - __bfloat162float(_h0));      \
            __nv_bfloat16 _l1 = __float2bfloat16(_s1 - __bfloat162float(_h1));      \
            __nv_bfloat16 _l2 = __float2bfloat16(_s2 - __bfloat162float(_h2));      \
            __nv_bfloat16 _l3 = __float2bfloat16(_s3 - __bfloat162float(_h3));      \
            _h[_j * 2 + 0] = (uint32_t)__bfloat16_as_ushort(_h0) | ((uint32_t)__bfloat16_as_ushort(_h1) << 16); \
            _h[_j * 2 + 1] = (uint32_t)__bfloat16_as_ushort(_h2) | ((uint32_t)__bfloat16_as_ushort(_h3) << 16); \
            _l[_j * 2 + 0] = (uint32_t)__bfloat16_as_ushort(_l0) | ((uint32_t)__bfloat16_as_ushort(_l1) << 16); \
            _l[_j * 2 + 1] = (uint32_t)__bfloat16_as_ushort(_l2) | ((uint32_t)__bfloat16_as_ushort(_l3) << 16); \
        }                                                                           \
        char* _d = smp + (st) * STAGE_B + _px * 64 + ((gcq ^ ((_px >> 1) & 3)) << 4); \
        *(uint4*)_d             = make_uint4(_h[0], _h[1], _h[2], _h[3]);            \
        *(uint4*)(_d + OFF_ALO) = make_uint4(_l[0], _l[1], _l[2], _l[3]);            \
    } while (0)

    // prologue: B stages 0,1 in flight; A(0) gathered directly
    COPY_B(0, 0); CP_COMMIT();
    COPY_B(1, 1); CP_COMMIT();
    __syncthreads();                       // metadata visible
    {
        float4 V[8];
        GATHER_LDG(0, 0, V); GATHER_STS(0, 0, 0, V);
        GATHER_LDG(0, 1, V); GATHER_STS(0, 0, 1, V);
    }
    CP_WAIT1();
    __syncthreads();                       // A(0)+B(0) ready

    float acc[4][8][4];
#pragma unroll
    for (int m = 0; m < 4; ++m)
#pragma unroll
        for (int n = 0; n < 8; ++n)
#pragma unroll
            for (int q = 0; q < 4; ++q) acc[m][n][q] = 0.f;

#define LOAD_FRAGS(stg, ko)                                                          \
    _Pragma("unroll")                                                                \
    for (int m = 0; m < 4; ++m) {                                                    \
        int row = wp * 64 + m * 16 + ar;                                             \
        uint32_t aaddr = (stg) + row * 64 +                                          \
            (uint32_t)(((((ko) * 2 + a16) ^ ((row >> 1) & 3)) << 4));                \
        asm volatile("ldmatrix.sync.aligned.m8n8.x4.shared.b16 {%0,%1,%2,%3}, [%4];" \
            : "=r"(ah[m][0]), "=r"(ah[m][1]), "=r"(ah[m][2]), "=r"(ah[m][3])         \
            : "r"(aaddr));                                                           \
        asm volatile("ldmatrix.sync.aligned.m8n8.x4.shared.b16 {%0,%1,%2,%3}, [%4];" \
            : "=r"(al[m][0]), "=r"(al[m][1]), "=r"(al[m][2]), "=r"(al[m][3])         \
            : "r"(aaddr + (uint32_t)OFF_ALO));                                       \
    }                                                                                \
    _Pragma("unroll")                                                                \
    for (int n = 0; n < 8; ++n) {                                                    \
        int row = wf * 64 + n * 8 + br;                                              \
        uint32_t baddr = (stg) + OFF_BHI + row * 64 +                                \
            (uint32_t)(((((ko) * 2 + b1) ^ ((row >> 1) & 3)) << 4));                 \
        asm volatile("ldmatrix.sync.aligned.m8n8.x2.shared.b16 {%0,%1}, [%2];"       \
            : "=r"(bh[n][0]), "=r"(bh[n][1]) : "r"(baddr));                          \
        asm volatile("ldmatrix.sync.aligned.m8n8.x2.shared.b16 {%0,%1}, [%2];"       \
            : "=r"(bl[n][0]), "=r"(bl[n][1]) : "r"(baddr + (uint32_t)(OFF_BLO - OFF_BHI))); \
    }

#define MMA(c, A0,A1,A2,A3,B0,B1) \
    asm volatile("mma.sync.aligned.m16n8k16.row.col.f32.bf16.bf16.f32 " \
        "{%0,%1,%2,%3}, {%4,%5,%6,%7}, {%8,%9}, {%0,%1,%2,%3};" \
        : "+f"((c)[0]), "+f"((c)[1]), "+f"((c)[2]), "+f"((c)[3]) \
        : "r"(A0), "r"(A1), "r"(A2), "r"(A3), "r"(B0), "r"(B1))

#define MMA_PASS(AF, BF)                                                             \
    _Pragma("unroll")                                                                \
    for (int m = 0; m < 4; ++m)                                                      \
        _Pragma("unroll")                                                            \
        for (int n = 0; n < 8; ++n)                                                  \
            MMA(acc[m][n], AF[m][0], AF[m][1], AF[m][2], AF[m][3], BF[n][0], BF[n][1]);

    for (int ks = 0; ks < KSTEPS; ++ks) {
        const uint32_t stg = smb + (ks % NSTG) * STAGE_B;
        const int nst = (ks + 1) % NSTG;
        const bool more = (ks + 1 < KSTEPS);

        uint32_t ah[4][4], al[4][4], bh[8][2], bl[8][2];
        float4 V[8];

        // ---- ko = 0 ----
        LOAD_FRAGS(stg, 0)
        if (more) GATHER_LDG(ks + 1, 0, V);     // half0 loads fly under MMAs
        MMA_PASS(ah, bh)
        MMA_PASS(al, bh)
        if (more) GATHER_STS(ks + 1, nst, 0, V);
        MMA_PASS(ah, bl)
        if (more) GATHER_LDG(ks + 1, 1, V);     // half1 loads fly under ko=1 MMAs

        // ---- ko = 1 ----
        LOAD_FRAGS(stg, 1)
        MMA_PASS(ah, bh)
        MMA_PASS(al, bh)
        if (more) GATHER_STS(ks + 1, nst, 1, V);
        MMA_PASS(ah, bl)

        // ---- next B stage + pipeline sync ----
        if (ks + 2 < KSTEPS) { COPY_B(ks + 2, (ks + 2) % NSTG); }
        CP_COMMIT();
        CP_WAIT1();
        __syncthreads();
    }
#undef MMA_PASS
#undef MMA
#undef LOAD_FRAGS

    // ---- epilogue: fragments -> out ----
#pragma unroll
    for (int m = 0; m < 4; ++m) {
        const int r0 = p0 + wp * 64 + m * 16 + (lane >> 2);
#pragma unroll
        for (int n = 0; n < 8; ++n) {
            const int col = wf * 64 + n * 8 + (lane & 3) * 2;
            *(float2*)(out + r0 * 256 + col)       = make_float2(acc[m][n][0], acc[m][n][1]);
            *(float2*)(out + (r0 + 8) * 256 + col) = make_float2(acc[m][n][2], acc[m][n][3]);
        }
    }
}

// ---------------------------------------------------------------------------
extern "C" void kernel_launch(void* const* d_in, const int* in_sizes, int n_in,
                              void* d_out, int out_size) {
    const float* x     = (const float*)d_in[0];   // [4,64,64,256]
    const float* w_off = (const float*)d_in[1];   // [3,3,256,27]
    const float* b_off = (const float*)d_in[2];   // [27]
    const float* filt  = (const float*)d_in[3];   // [256,256,3,3]
    float* out = (float*)d_out;                   // [4,64,64,256]

    cudaFuncSetAttribute(dcn_gemm_kernel, cudaFuncAttributeMaxDynamicSharedMemorySize, SMEM_BYTES);

    split_filt_kernel<<<2304, 256>>>(filt);
    offset_meta_kernel<<<512, 256>>>(x, w_off, b_off);
    dcn_gemm_kernel<<<128, 256, SMEM_BYTES>>>(x, out);
}

// round 10
// speedup vs baseline: 3.7220x; 1.3676x over previous
#include <cuda_runtime.h>
#include <cuda_bf16.h>
#include <cstdint>

// Problem constants
#define NPIX   16384       // B*H*W = 4*64*64
#define KSTEPS 72          // 9 taps * 8 k32-steps

// Scratch (allocation-free: __device__ globals)
__device__ int4   g_midx[9 * NPIX];          // corner element offsets (pre-multiplied by C)
__device__ float4 g_mw[9 * NPIX];            // bilinear*mask*valid weights
// Main-filter B operand, split bf16 hi/lo: [kstep][f(256)][ch(32)]
__device__ __nv_bfloat16 g_wbhi[KSTEPS * 256 * 32];
__device__ __nv_bfloat16 g_wblo[KSTEPS * 256 * 32];
// Offset-conv B operand, split bf16 hi/lo: [kstep][o(32, 27 used)][ch(32)]
__device__ __nv_bfloat16 g_obhi[KSTEPS * 32 * 32];
__device__ __nv_bfloat16 g_oblo[KSTEPS * 32 * 32];

__device__ __forceinline__ uint32_t smem_u32(const void* p) {
    uint32_t a;
    asm("{ .reg .u64 t; cvta.to.shared.u64 t, %1; cvt.u32.u64 %0, t; }" : "=r"(a) : "l"(p));
    return a;
}
#define CP_ASYNC16(dst_u32, src_ptr) \
    asm volatile("cp.async.cg.shared.global [%0], [%1], 16;" :: "r"(dst_u32), "l"(src_ptr))
#define CP_COMMIT()  asm volatile("cp.async.commit_group;" ::: "memory")
#define CP_WAIT1()   asm volatile("cp.async.wait_group 1;" ::: "memory")

// split one fp32 -> packed bf16 hi/lo helper
__device__ __forceinline__ void split_bf16(float s, uint16_t& h, uint16_t& l) {
    __nv_bfloat16 hb = __float2bfloat16(s);
    __nv_bfloat16 lb = __float2bfloat16(s - __bfloat162float(hb));
    h = __bfloat16_as_ushort(hb);
    l = __bfloat16_as_ushort(lb);
}

// ---------------------------------------------------------------------------
// Kernel 1: split filt [F,C,3,3] -> bf16 hi/lo in [kstep][f][32] layout
// ---------------------------------------------------------------------------
__global__ void split_filt_kernel(const float* __restrict__ filt) {
    int i = blockIdx.x * 256 + threadIdx.x;    // 9*256*256
    int c  = i & 255;
    int f  = (i >> 8) & 255;
    int kk = i >> 16;
    float w = filt[(f * 256 + c) * 9 + kk];
    uint16_t h, l;
    split_bf16(w, h, l);
    int kstep = kk * 8 + (c >> 5);
    int idx   = (kstep * 256 + f) * 32 + (c & 31);
    g_wbhi[idx] = __ushort_as_bfloat16(h);
    g_wblo[idx] = __ushort_as_bfloat16(l);
}

// ---------------------------------------------------------------------------
// Kernel 1b: split w_offset [3,3,256,27] -> [kstep][o(32)][ch(32)] hi/lo
// rows 27..31 zero-padded.
// ---------------------------------------------------------------------------
__global__ void split_woff_kernel(const float* __restrict__ w_off) {
    int i = blockIdx.x * 256 + threadIdx.x;    // 72*32*32 = 73728
    int ch = i & 31;
    int o  = (i >> 5) & 31;
    int ks = i >> 10;
    int tap = ks >> 3;
    int c   = (ks & 7) * 32 + ch;
    float w = (o < 27) ? w_off[(tap * 256 + c) * 27 + o] : 0.f;
    uint16_t h, l;
    split_bf16(w, h, l);
    g_obhi[i] = __ushort_as_bfloat16(h);
    g_oblo[i] = __ushort_as_bfloat16(l);
}

// ---------------------------------------------------------------------------
// Kernel 2: offset conv as tensor-core GEMM + fused metadata epilogue.
// CTA = 128 px x 32 outs (27 used), grid 128 = 1 wave, 256 thr = 8 warps,
// warp tile 16 px x 32 o. A built from shifted x taps (zero border), split
// bf16 hi/lo, 2-stage; B via cp.async, 3-stage. 3-pass split-precision.
// Epilogue: acc -> smem -> sigmoid/floor/metadata -> g_midx/g_mw.
// ---------------------------------------------------------------------------
// smem layout (bytes):
#define OA_ST   16384                 // per A stage: hi 8192 + lo 8192
#define OB_BASE 32768
#define OB_ST   4096                  // per B stage: hi 2048 + lo 2048
#define OEPI    45056                 // 128 x 36 floats = 18432
#define OSMEM   63488

__global__ __launch_bounds__(256, 1)
void offset_gemm_kernel(const float* __restrict__ x, const float* __restrict__ b_off,
                        float* __restrict__ dummy) {
    extern __shared__ char smraw[];
    char* smp = smraw;
    const uint32_t smb = smem_u32(smraw);

    const int tid  = threadIdx.x;
    const int wid  = tid >> 5;
    const int lane = tid & 31;
    const int p0   = blockIdx.x * 128;

    // gather mapping: thread -> (px, 16-ch half)
    const int gpx  = tid >> 1;             // 0..127
    const int ghalf = tid & 1;
    const int gp   = p0 + gpx;
    const int gb   = gp >> 12;
    const int gy   = (gp >> 6) & 63;
    const int gx   = gp & 63;

    // ldmatrix lane addressing
    const int ar  = lane & 15;
    const int a16 = lane >> 4;
    const int br  = lane & 7;
    const int b1  = (lane >> 3) & 1;

#define OCOPY_B(ks, st) do {                                                        \
        int _half = tid >> 7;               /* 0 = hi, 1 = lo */                    \
        int _t = tid & 127;                                                         \
        int _row = _t >> 2, _ch4 = _t & 3;                                          \
        const __nv_bfloat16* _src = (_half ? g_oblo : g_obhi) + (ks) * 1024 + _row * 32 + _ch4 * 8; \
        uint32_t _d = smb + OB_BASE + (st) * OB_ST + _half * 2048                   \
                      + _row * 64 + ((_ch4 ^ ((_row >> 1) & 3)) << 4);              \
        CP_ASYNC16(_d, (const char*)_src);                                          \
    } while (0)

// load 16 ch of shifted-tap x for kstep ksn into V[4]
#define OALDG(ksn, V) do {                                                          \
        const int _tap = (ksn) >> 3;                                                \
        const int _ki = _tap / 3, _kj = _tap - _ki * 3;                             \
        const int _ys = gy - 1 + _ki, _xs = gx - 1 + _kj;                           \
        if ((unsigned)_ys < 64u && (unsigned)_xs < 64u) {                           \
            const int _c = ((ksn) & 7) * 32 + ghalf * 16;                           \
            const float* _p = x + ((((gb << 12) + (_ys << 6) + _xs) << 8) + _c);    \
            V[0] = __ldg((const float4*)_p);                                        \
            V[1] = __ldg((const float4*)(_p + 4));                                  \
            V[2] = __ldg((const float4*)(_p + 8));                                  \
            V[3] = __ldg((const float4*)(_p + 12));                                 \
        } else {                                                                    \
            V[0] = V[1] = V[2] = V[3] = make_float4(0.f, 0.f, 0.f, 0.f);            \
        }                                                                           \
    } while (0)

// convert V -> bf16 hi/lo, store to A stage st
#define OASTS(st, V) do {                                                           \
        uint32_t _h[4], _l[4];                                                      \
        _Pragma("unroll")                                                           \
        for (int _j = 0; _j < 4; ++_j) {                                            \
            uint16_t _h0,_l0,_h1,_l1;                                               \
            split_bf16(V[_j].x, _h0, _l0); split_bf16(V[_j].y, _h1, _l1);           \
            _h[_j] = (uint32_t)_h0 | ((uint32_t)_h1 << 16);                         \
            _l[_j] = (uint32_t)_l0 | ((uint32_t)_l1 << 16);                         \
            uint16_t _h2,_l2,_h3,_l3;                                               \
            split_bf16(V[_j].z, _h2, _l2); split_bf16(V[_j].w, _h3, _l3);            \
            _h[_j] |= 0; _l[_j] |= 0;                                               \
            /* pack 4 per uint2 below */                                            \
            Vh[_j * 2 + 0] = (uint32_t)_h0 | ((uint32_t)_h1 << 16);                 \
            Vh[_j * 2 + 1] = (uint32_t)_h2 | ((uint32_t)_h3 << 16);                 \
            Vl[_j * 2 + 0] = (uint32_t)_l0 | ((uint32_t)_l1 << 16);                 \
            Vl[_j * 2 + 1] = (uint32_t)_l2 | ((uint32_t)_l3 << 16);                 \
        }                                                                           \
        char* _dbase = smp + (st) * OA_ST + gpx * 64;                               \
        _Pragma("unroll")                                                           \
        for (int _q = 0; _q < 2; ++_q) {                                            \
            int _chunk = ghalf * 2 + _q;                                            \
            char* _d = _dbase + ((_chunk ^ ((gpx >> 1) & 3)) << 4);                 \
            *(uint4*)_d          = make_uint4(Vh[_q*4+0], Vh[_q*4+1], Vh[_q*4+2], Vh[_q*4+3]); \
            *(uint4*)(_d + 8192) = make_uint4(Vl[_q*4+0], Vl[_q*4+1], Vl[_q*4+2], Vl[_q*4+3]); \
        }                                                                           \
    } while (0)

    uint32_t Vh[8], Vl[8];

    // prologue
    OCOPY_B(0, 0); CP_COMMIT();
    OCOPY_B(1, 1); CP_COMMIT();
    {
        float4 V[4];
        OALDG(0, V);
        OASTS(0, V);
    }
    CP_WAIT1();
    __syncthreads();

    float acc[4][4];
#pragma unroll
    for (int n = 0; n < 4; ++n)
#pragma unroll
        for (int q = 0; q < 4; ++q) acc[n][q] = 0.f;

#define OMMA(c, A0,A1,A2,A3,B0,B1) \
    asm volatile("mma.sync.aligned.m16n8k16.row.col.f32.bf16.bf16.f32 " \
        "{%0,%1,%2,%3}, {%4,%5,%6,%7}, {%8,%9}, {%0,%1,%2,%3};" \
        : "+f"((c)[0]), "+f"((c)[1]), "+f"((c)[2]), "+f"((c)[3]) \
        : "r"(A0), "r"(A1), "r"(A2), "r"(A3), "r"(B0), "r"(B1))

    for (int ks = 0; ks < KSTEPS; ++ks) {
        const uint32_t astg = smb + (ks & 1) * OA_ST;
        const uint32_t bstg = smb + OB_BASE + (ks % 3) * OB_ST;
        const bool more = (ks + 1 < KSTEPS);

        uint32_t ah[2][4], al[2][4], bh[2][4][2], bl[2][4][2];
#pragma unroll
        for (int ko = 0; ko < 2; ++ko) {
            int arow = wid * 16 + ar;
            uint32_t aaddr = astg + arow * 64 +
                (uint32_t)(((ko * 2 + a16) ^ ((arow >> 1) & 3)) << 4);
            asm volatile("ldmatrix.sync.aligned.m8n8.x4.shared.b16 {%0,%1,%2,%3}, [%4];"
                : "=r"(ah[ko][0]), "=r"(ah[ko][1]), "=r"(ah[ko][2]), "=r"(ah[ko][3])
                : "r"(aaddr));
            asm volatile("ldmatrix.sync.aligned.m8n8.x4.shared.b16 {%0,%1,%2,%3}, [%4];"
                : "=r"(al[ko][0]), "=r"(al[ko][1]), "=r"(al[ko][2]), "=r"(al[ko][3])
                : "r"(aaddr + 8192u));
#pragma unroll
            for (int n = 0; n < 4; ++n) {
                int brow = n * 8 + br;
                uint32_t baddr = bstg + brow * 64 +
                    (uint32_t)(((ko * 2 + b1) ^ ((brow >> 1) & 3)) << 4);
                asm volatile("ldmatrix.sync.aligned.m8n8.x2.shared.b16 {%0,%1}, [%2];"
                    : "=r"(bh[ko][n][0]), "=r"(bh[ko][n][1]) : "r"(baddr));
                asm volatile("ldmatrix.sync.aligned.m8n8.x2.shared.b16 {%0,%1}, [%2];"
                    : "=r"(bl[ko][n][0]), "=r"(bl[ko][n][1]) : "r"(baddr + 2048u));
            }
        }

        float4 V[4];
        if (more) OALDG(ks + 1, V);

#pragma unroll
        for (int ko = 0; ko < 2; ++ko) {
#pragma unroll
            for (int n = 0; n < 4; ++n)
                OMMA(acc[n], ah[ko][0], ah[ko][1], ah[ko][2], ah[ko][3], bh[ko][n][0], bh[ko][n][1]);
#pragma unroll
            for (int n = 0; n < 4; ++n)
                OMMA(acc[n], al[ko][0], al[ko][1], al[ko][2], al[ko][3], bh[ko][n][0], bh[ko][n][1]);
#pragma unroll
            for (int n = 0; n < 4; ++n)
                OMMA(acc[n], ah[ko][0], ah[ko][1], ah[ko][2], ah[ko][3], bl[ko][n][0], bl[ko][n][1]);
        }

        if (more) OASTS((ks + 1) & 1, V);
        if (ks + 2 < KSTEPS) OCOPY_B(ks + 2, (ks + 2) % 3);
        CP_COMMIT();
        CP_WAIT1();
        __syncthreads();
    }
#undef OMMA

    // ---- epilogue: acc -> smem [128][36] ----
    float* epi = (float*)(smp + OEPI);
    {
        const int r0 = wid * 16 + (lane >> 2);
#pragma unroll
        for (int n = 0; n < 4; ++n) {
            const int col = n * 8 + (lane & 3) * 2;
            epi[r0 * 36 + col]           = acc[n][0];
            epi[r0 * 36 + col + 1]       = acc[n][1];
            epi[(r0 + 8) * 36 + col]     = acc[n][2];
            epi[(r0 + 8) * 36 + col + 1] = acc[n][3];
        }
    }
    __syncthreads();

    // ---- metadata: 128 px x 9 taps ----
    for (int i = tid; i < 1152; i += 256) {
        int px = i / 9;
        int kk = i - px * 9;
        int gpix = p0 + px;
        int bb = gpix >> 12;
        int yy = (gpix >> 6) & 63;
        int xx = gpix & 63;

        float o1v = epi[px * 36 + kk]      + __ldg(b_off + kk);
        float o2v = epi[px * 36 + 9 + kk]  + __ldg(b_off + 9 + kk);
        float mlg = epi[px * 36 + 18 + kk] + __ldg(b_off + 18 + kk);
        float mv  = 1.f / (1.f + __expf(-mlg));

        float pyv = o1v + (float)(yy - 1 + kk / 3);
        float pxv = o2v + (float)(xx - 1 + kk % 3);
        float yf = floorf(pyv), xf = floorf(pxv);
        float dy = pyv - yf, dx = pxv - xf;
        int iy = (int)yf, ix = (int)xf;

        int base = bb << 12;
        int yc0 = min(max(iy, 0), 63),     yc1 = min(max(iy + 1, 0), 63);
        int xc0 = min(max(ix, 0), 63),     xc1 = min(max(ix + 1, 0), 63);
        float vy0 = ((unsigned)iy       < 64u) ? 1.f : 0.f;
        float vy1 = ((unsigned)(iy + 1) < 64u) ? 1.f : 0.f;
        float vx0 = ((unsigned)ix       < 64u) ? 1.f : 0.f;
        float vx1 = ((unsigned)(ix + 1) < 64u) ? 1.f : 0.f;

        g_midx[kk * NPIX + gpix] = make_int4(((base + (yc0 << 6) + xc0) << 8),
                                             ((base + (yc0 << 6) + xc1) << 8),
                                             ((base + (yc1 << 6) + xc0) << 8),
                                             ((base + (yc1 << 6) + xc1) << 8));
        g_mw[kk * NPIX + gpix] = make_float4((1.f - dy) * (1.f - dx) * mv * vy0 * vx0,
                                             (1.f - dy) * dx         * mv * vy0 * vx1,
                                             dy         * (1.f - dx) * mv * vy1 * vx0,
                                             dy         * dx         * mv * vy1 * vx1);
    }
    (void)dummy;
}

// ---------------------------------------------------------------------------
// Kernel 3: FUSED gather + bf16 GEMM (unchanged from R9 winner).
// ---------------------------------------------------------------------------
#define OFF_ALO 8192
#define OFF_BHI 16384
#define OFF_BLO 32768
#define STAGE_B 49152
#define NSTG    3
#define META_OFF (NSTG * STAGE_B)                    // 147456
#define SMEM_BYTES (META_OFF + 1152 * 16 * 2)        // 184320

__global__ __launch_bounds__(256, 1)
void dcn_gemm_kernel(const float* __restrict__ x, float* __restrict__ out) {
    extern __shared__ char smraw[];
    char* smp = smraw;
    const uint32_t smb = smem_u32(smraw);

    int4*   mi_s = (int4*)(smp + META_OFF);
    float4* mw_s = (float4*)(mi_s + 1152);

    const int tid  = threadIdx.x;
    const int wid  = tid >> 5;
    const int lane = tid & 31;
    const int p0   = blockIdx.x * 128;
    const int wp   = wid >> 2;
    const int wf   = wid & 3;

    const int gpx = tid >> 2;
    const int gcq = tid & 3;

    const int ar  = lane & 15;
    const int a16 = lane >> 4;
    const int br  = lane & 7;
    const int b1  = (lane >> 3) & 1;

    for (int i = tid; i < 1152; i += 256) {
        int kk = i >> 7, pp = i & 127;
        mi_s[i] = g_midx[kk * NPIX + p0 + pp];
        mw_s[i] = g_mw[kk * NPIX + p0 + pp];
    }

#define COPY_B(ks, st) do {                                                         \
        uint32_t _s = smb + (st) * STAGE_B + OFF_BHI;                               \
        _Pragma("unroll")                                                           \
        for (int _i = 0; _i < 4; ++_i) {                                            \
            int _idx = tid + _i * 256;                                              \
            int _row = _idx >> 2, _ch = _idx & 3;                                   \
            uint32_t _d = _s + _row * 64 + ((_ch ^ ((_row >> 1) & 3)) << 4);        \
            const char* _bh = (const char*)(g_wbhi + ((ks) * 256 + _row) * 32 + _ch * 8); \
            const char* _bl = (const char*)(g_wblo + ((ks) * 256 + _row) * 32 + _ch * 8); \
            CP_ASYNC16(_d, _bh);                                                    \
            CP_ASYNC16(_d + (OFF_BLO - OFF_BHI), _bl);                              \
        }                                                                           \
    } while (0)

#define GATHER_LDG(ksn, po, V) do {                                                 \
        const int _kk = (ksn) >> 3;                                                 \
        const int _cb = ((ksn) & 7) * 32;                                           \
        const int _px = (po) * 64 + gpx;                                            \
        const int4 _mi = mi_s[_kk * 128 + _px];                                     \
        _Pragma("unroll")                                                           \
        for (int _j = 0; _j < 2; ++_j) {                                            \
            const int _c = _cb + gcq * 8 + _j * 4;                                  \
            V[_j * 4 + 0] = __ldg((const float4*)(x + _mi.x + _c));                 \
            V[_j * 4 + 1] = __ldg((const float4*)(x + _mi.y + _c));                 \
            V[_j * 4 + 2] = __ldg((const float4*)(x + _mi.z + _c));                 \
            V[_j * 4 + 3] = __ldg((const float4*)(x + _mi.w + _c));                 \
        }                                                                           \
    } while (0)

#define GATHER_STS(ksn, st, po, V) do {                                             \
        const int _kk = (ksn) >> 3;                                                 \
        const int _px = (po) * 64 + gpx;                                            \
        const float4 _w = mw_s[_kk * 128 + _px];                                    \
        uint32_t _h[4], _l[4];                                                      \
        _Pragma("unroll")                                                           \
        for (int _j = 0; _j < 2; ++_j) {                                            \
            float4 _v00 = V[_j * 4 + 0], _v01 = V[_j * 4 + 1];                      \
            float4 _v10 = V[_j * 4 + 2], _v11 = V[_j * 4 + 3];                      \
            float _s0 = _v00.x * _w.x + _v01.x * _w.y + _v10.x * _w.z + _v11.x * _w.w; \
            float _s1 = _v00.y * _w.x + _v01.y * _w.y + _v10.y * _w.z + _v11.y * _w.w; \
            float _s2 = _v00.z * _w.x + _v01.z * _w.y + _v10.z * _w.z + _v11.z * _w.w; \
            float _s3 = _v00.w * _w.x + _v01.w * _w.y + _v10.w * _w.z + _v11.w * _w.w; \
            uint16_t _h0,_l0,_h1,_l1,_h2,_l2,_h3,_l3;                               \
            split_bf16(_s0, _h0, _l0); split_bf16(_s1, _h1, _l1);                   \
            split_bf16(_s2, _h2, _l2); split_bf16(_s3, _h3, _l3);                   \
            _h[_j * 2 + 0] = (uint32_t)_h0 | ((uint32_t)_h1 << 16);                 \
            _h[_j * 2 + 1] = (uint32_t)_h2 | ((uint32_t)_h3 << 16);                 \
            _l[_j * 2 + 0] = (uint32_t)_l0 | ((uint32_t)_l1 << 16);                 \
            _l[_j * 2 + 1] = (uint32_t)_l2 | ((uint32_t)_l3 << 16);                 \
        }                                                                           \
        char* _d = smp + (st) * STAGE_B + _px * 64 + ((gcq ^ ((_px >> 1) & 3)) << 4); \
        *(uint4*)_d             = make_uint4(_h[0], _h[1], _h[2], _h[3]);            \
        *(uint4*)(_d + OFF_ALO) = make_uint4(_l[0], _l[1], _l[2], _l[3]);            \
    } while (0)

    COPY_B(0, 0); CP_COMMIT();
    COPY_B(1, 1); CP_COMMIT();
    __syncthreads();
    {
        float4 V[8];
        GATHER_LDG(0, 0, V); GATHER_STS(0, 0, 0, V);
        GATHER_LDG(0, 1, V); GATHER_STS(0, 0, 1, V);
    }
    CP_WAIT1();
    __syncthreads();

    float acc[4][8][4];
#pragma unroll
    for (int m = 0; m < 4; ++m)
#pragma unroll
        for (int n = 0; n < 8; ++n)
#pragma unroll
            for (int q = 0; q < 4; ++q) acc[m][n][q] = 0.f;

#define LOAD_FRAGS(stg, ko)                                                          \
    _Pragma("unroll")                                                                \
    for (int m = 0; m < 4; ++m) {                                                    \
        int row = wp * 64 + m * 16 + ar;                                             \
        uint32_t aaddr = (stg) + row * 64 +                                          \
            (uint32_t)(((((ko) * 2 + a16) ^ ((row >> 1) & 3)) << 4));                \
        asm volatile("ldmatrix.sync.aligned.m8n8.x4.shared.b16 {%0,%1,%2,%3}, [%4];" \
            : "=r"(ah[m][0]), "=r"(ah[m][1]), "=r"(ah[m][2]), "=r"(ah[m][3])         \
            : "r"(aaddr));                                                           \
        asm volatile("ldmatrix.sync.aligned.m8n8.x4.shared.b16 {%0,%1,%2,%3}, [%4];" \
            : "=r"(al[m][0]), "=r"(al[m][1]), "=r"(al[m][2]), "=r"(al[m][3])         \
            : "r"(aaddr + (uint32_t)OFF_ALO));                                       \
    }                                                                                \
    _Pragma("unroll")                                                                \
    for (int n = 0; n < 8; ++n) {                                                    \
        int row = wf * 64 + n * 8 + br;                                              \
        uint32_t baddr = (stg) + OFF_BHI + row * 64 +                                \
            (uint32_t)(((((ko) * 2 + b1) ^ ((row >> 1) & 3)) << 4));                 \
        asm volatile("ldmatrix.sync.aligned.m8n8.x2.shared.b16 {%0,%1}, [%2];"       \
            : "=r"(bh[n][0]), "=r"(bh[n][1]) : "r"(baddr));                          \
        asm volatile("ldmatrix.sync.aligned.m8n8.x2.shared.b16 {%0,%1}, [%2];"       \
            : "=r"(bl[n][0]), "=r"(bl[n][1]) : "r"(baddr + (uint32_t)(OFF_BLO - OFF_BHI))); \
    }

#define MMA(c, A0,A1,A2,A3,B0,B1) \
    asm volatile("mma.sync.aligned.m16n8k16.row.col.f32.bf16.bf16.f32 " \
        "{%0,%1,%2,%3}, {%4,%5,%6,%7}, {%8,%9}, {%0,%1,%2,%3};" \
        : "+f"((c)[0]), "+f"((c)[1]), "+f"((c)[2]), "+f"((c)[3]) \
        : "r"(A0), "r"(A1), "r"(A2), "r"(A3), "r"(B0), "r"(B1))

#define MMA_PASS(AF, BF)                                                             \
    _Pragma("unroll")                                                                \
    for (int m = 0; m < 4; ++m)                                                      \
        _Pragma("unroll")                                                            \
        for (int n = 0; n < 8; ++n)                                                  \
            MMA(acc[m][n], AF[m][0], AF[m][1], AF[m][2], AF[m][3], BF[n][0], BF[n][1]);

    for (int ks = 0; ks < KSTEPS; ++ks) {
        const uint32_t stg = smb + (ks % NSTG) * STAGE_B;
        const int nst = (ks + 1) % NSTG;
        const bool more = (ks + 1 < KSTEPS);

        uint32_t ah[4][4], al[4][4], bh[8][2], bl[8][2];
        float4 V[8];

        LOAD_FRAGS(stg, 0)
        if (more) GATHER_LDG(ks + 1, 0, V);
        MMA_PASS(ah, bh)
        MMA_PASS(al, bh)
        if (more) GATHER_STS(ks + 1, nst, 0, V);
        MMA_PASS(ah, bl)
        if (more) GATHER_LDG(ks + 1, 1, V);

        LOAD_FRAGS(stg, 1)
        MMA_PASS(ah, bh)
        MMA_PASS(al, bh)
        if (more) GATHER_STS(ks + 1, nst, 1, V);
        MMA_PASS(ah, bl)

        if (ks + 2 < KSTEPS) { COPY_B(ks + 2, (ks + 2) % NSTG); }
        CP_COMMIT();
        CP_WAIT1();
        __syncthreads();
    }
#undef MMA_PASS
#undef MMA
#undef LOAD_FRAGS

#pragma unroll
    for (int m = 0; m < 4; ++m) {
        const int r0 = p0 + wp * 64 + m * 16 + (lane >> 2);
#pragma unroll
        for (int n = 0; n < 8; ++n) {
            const int col = wf * 64 + n * 8 + (lane & 3) * 2;
            *(float2*)(out + r0 * 256 + col)       = make_float2(acc[m][n][0], acc[m][n][1]);
            *(float2*)(out + (r0 + 8) * 256 + col) = make_float2(acc[m][n][2], acc[m][n][3]);
        }
    }
}

// ---------------------------------------------------------------------------
extern "C" void kernel_launch(void* const* d_in, const int* in_sizes, int n_in,
                              void* d_out, int out_size) {
    const float* x     = (const float*)d_in[0];   // [4,64,64,256]
    const float* w_off = (const float*)d_in[1];   // [3,3,256,27]
    const float* b_off = (const float*)d_in[2];   // [27]
    const float* filt  = (const float*)d_in[3];   // [256,256,3,3]
    float* out = (float*)d_out;                   // [4,64,64,256]

    cudaFuncSetAttribute(dcn_gemm_kernel, cudaFuncAttributeMaxDynamicSharedMemorySize, SMEM_BYTES);
    cudaFuncSetAttribute(offset_gemm_kernel, cudaFuncAttributeMaxDynamicSharedMemorySize, OSMEM);

    split_filt_kernel<<<2304, 256>>>(filt);
    split_woff_kernel<<<288, 256>>>(w_off);
    offset_gemm_kernel<<<128, 256, OSMEM>>>(x, b_off, out);
    dcn_gemm_kernel<<<128, 256, SMEM_BYTES>>>(x, out);
}